// round 1
// baseline (speedup 1.0000x reference)
#include <cuda_runtime.h>

// ---------------------------------------------------------------------------
// ResidualBlock: y = feat@Wnin + subconv(bnrelu(subconv(bnrelu(feat),W1)),W2)
// N=100000 sites, A=64, B=128, K=27 offsets. All fp32 (exact numerics).
// Strategy: rulebook-compacted gather-GEMM with packed f32x2 FMA (B300).
// ---------------------------------------------------------------------------

#define KK   27
#define AA   64
#define BBC  128
#define NMAX 100000
#define PB   132     // stats partial blocks

// ---------------- static device scratch (no allocs allowed) ----------------
__device__ float g_out1[(size_t)NMAX * BBC];   // conv1 output (pre-BN2)
__device__ int   g_idx[KK * NMAX];             // rulebook: per-offset site lists
__device__ int   g_cnt[KK];                    // rulebook counts
__device__ int   g_mask_u8;                    // 1 if mask is 1-byte bool layout
__device__ float g_ps[PB * BBC];               // stats partial sums
__device__ float g_pq[PB * BBC];               // stats partial sums of squares
__device__ float g_scale1[AA],  g_bias1[AA];   // folded BN1 affine
__device__ float g_scale2[BBC], g_bias2[BBC];  // folded BN2 affine

// ---------------- packed f32x2 helpers (2x fp32 FMA rate on sm_103a) -------
__device__ __forceinline__ unsigned long long pk2(float x) {
    unsigned long long r;
    asm("mov.b64 %0, {%1, %1};" : "=l"(r) : "f"(x));
    return r;
}
__device__ __forceinline__ void fma2(unsigned long long& acc,
                                     unsigned long long a,
                                     unsigned long long b) {
    asm("fma.rn.f32x2 %0, %1, %2, %0;" : "+l"(acc) : "l"(a), "l"(b));
}
__device__ __forceinline__ float2 up2(unsigned long long v) {
    float2 f;
    asm("mov.b64 {%0, %1}, %2;" : "=f"(f.x), "=f"(f.y) : "l"(v));
    return f;
}

// ---------------- mask layout detection + counter reset --------------------
// Center offset (k=13) is always true. If mask were int32, byte (i*27+13)
// is a high byte of some int for most i -> 0 -> detection fails fast.
__global__ void k_detect(const unsigned char* __restrict__ m8) {
    int t = threadIdx.x;           // 256 threads, N >= 256 guaranteed
    if (t < KK) g_cnt[t] = 0;
    int ok = (m8[t * KK + KK / 2] != 0) ? 1 : 0;
    int all = __syncthreads_and(ok);
    if (t == 0) g_mask_u8 = all;
}

// ---------------- BN stats: per-channel sum / sumsq partials ---------------
template <int CH, int RG>
__global__ void k_stats(const float* __restrict__ x, int N) {
    int c = threadIdx.x, r = threadIdx.y;
    float s = 0.f, q = 0.f;
    for (int i = blockIdx.x * RG + r; i < N; i += gridDim.x * RG) {
        float v = x[(size_t)i * CH + c];
        s += v; q += v * v;
    }
    __shared__ float sh[RG][CH];
    __shared__ float shq[RG][CH];
    sh[r][c] = s; shq[r][c] = q;
    __syncthreads();
    if (r == 0) {
#pragma unroll
        for (int j = 1; j < RG; j++) { s += sh[j][c]; q += shq[j][c]; }
        g_ps[blockIdx.x * CH + c] = s;
        g_pq[blockIdx.x * CH + c] = q;
    }
}

template <int CH>
__global__ void k_fin(const float* __restrict__ gamma,
                      const float* __restrict__ beta,
                      float* __restrict__ scl, float* __restrict__ bia, int N) {
    int c = threadIdx.x;
    float s = 0.f, q = 0.f;
    for (int b = 0; b < PB; b++) { s += g_ps[b * CH + c]; q += g_pq[b * CH + c]; }
    float mu  = s / (float)N;
    float var = q / (float)N - mu * mu;
    if (var < 0.f) var = 0.f;
    float rs = rsqrtf(var + 1e-4f);
    float sc = gamma[c] * rs;
    scl[c] = sc;
    bia[c] = beta[c] - mu * sc;
}

// ---------------- rulebook build (compact valid (site,offset) pairs) -------
__global__ void k_rule(const void* __restrict__ mp, int N) {
    int i = blockIdx.x * blockDim.x + threadIdx.x;
    if (i >= N) return;
    const bool u8 = (g_mask_u8 != 0);
    const unsigned char* m8  = (const unsigned char*)mp;
    const int*           m32 = (const int*)mp;
#pragma unroll
    for (int k = 0; k < KK; k++) {
        bool m = u8 ? (m8[(size_t)i * KK + k] != 0)
                    : (m32[(size_t)i * KK + k] != 0);
        if (m) {
            int p = atomicAdd(&g_cnt[k], 1);
            g_idx[k * N + p] = i;
        }
    }
}

// ---------------- zero fill -------------------------------------------------
__global__ void k_zero(float* __restrict__ p, size_t n4) {
    size_t i = blockIdx.x * (size_t)blockDim.x + threadIdx.x;
    if (i < n4) ((float4*)p)[i] = make_float4(0.f, 0.f, 0.f, 0.f);
}

// ---------------- gather-GEMM pass ------------------------------------------
// One pass = one kernel offset k. Block: 128 sites x 128 cols, BK=32.
// 256 threads, 8x8 register micro-tile held as 32 packed f32x2 accumulators.
// BN affine + ReLU fused into the gather. Output += per pass (rows unique
// within a pass -> no races; pass order fixed -> bitwise deterministic).
template <int CIN, bool GATHER, bool AFFINE, bool ACCUM>
__global__ void __launch_bounds__(256, 2) k_gemm(
    const float* __restrict__ src, const float* __restrict__ Wk,
    float* __restrict__ out, const int* __restrict__ nbr, int k,
    const float* __restrict__ scl, const float* __restrict__ bia, int N) {

    const int cnt  = GATHER ? g_cnt[k] : N;
    const int tile = blockIdx.x * 128;
    if (tile >= cnt) return;

    __shared__ float As[128 * 33];            // 32-wide chunk + pad
    __shared__ __align__(16) float Bs[32 * 128];
    __shared__ int   s_src[128];
    __shared__ int   s_dst[128];
    __shared__ float s_s[CIN];
    __shared__ float s_b[CIN];

    const int tid  = threadIdx.x;
    const int lane = tid & 31, warp = tid >> 5;
    const int tx   = tid & 15, ty   = tid >> 4;

    if (tid < 128) {
        int gr = tile + tid;
        int i = -1, sr = -1;
        if (gr < cnt) {
            i  = GATHER ? g_idx[k * N + gr] : gr;
            sr = GATHER ? nbr[(size_t)i * KK + k] : i;
        }
        s_dst[tid] = i;
        s_src[tid] = sr;
    }
    if (AFFINE) {
        for (int c = tid; c < CIN; c += 256) { s_s[c] = scl[c]; s_b[c] = bia[c]; }
    }
    __syncthreads();

    unsigned long long acc[8][4];
#pragma unroll
    for (int a = 0; a < 8; a++)
#pragma unroll
        for (int b = 0; b < 4; b++) acc[a][b] = 0ull;

#pragma unroll
    for (int ch = 0; ch < CIN; ch += 32) {
        // W chunk: 32x128 floats, contiguous from Wk + ch*128
        {
            const float4* ws = (const float4*)(Wk + (size_t)ch * 128);
            float4*       bd = (float4*)Bs;
#pragma unroll
            for (int j = 0; j < 4; j++) bd[tid + j * 256] = ws[tid + j * 256];
        }
        // gathered A chunk with fused BN affine + ReLU
        for (int r = warp; r < 128; r += 8) {
            int sr = s_src[r];
            float v = 0.f;
            if (sr >= 0) {
                v = src[(size_t)sr * CIN + ch + lane];
                if (AFFINE) v = fmaxf(v * s_s[ch + lane] + s_b[ch + lane], 0.f);
            }
            As[r * 33 + lane] = v;
        }
        __syncthreads();

#pragma unroll
        for (int kk = 0; kk < 32; kk++) {
            const unsigned long long* bp =
                (const unsigned long long*)(Bs + kk * 128 + tx * 8);
            unsigned long long b0 = bp[0], b1 = bp[1], b2 = bp[2], b3 = bp[3];
#pragma unroll
            for (int dr = 0; dr < 8; dr++) {
                float av = As[(ty * 8 + dr) * 33 + kk];
                unsigned long long aa = pk2(av);
                fma2(acc[dr][0], aa, b0);
                fma2(acc[dr][1], aa, b1);
                fma2(acc[dr][2], aa, b2);
                fma2(acc[dr][3], aa, b3);
            }
        }
        __syncthreads();
    }

#pragma unroll
    for (int dr = 0; dr < 8; dr++) {
        int i = s_dst[ty * 8 + dr];
        if (i < 0) continue;
        float* op = out + (size_t)i * 128 + tx * 8;
        float2 v0 = up2(acc[dr][0]), v1 = up2(acc[dr][1]);
        float2 v2 = up2(acc[dr][2]), v3 = up2(acc[dr][3]);
        if (ACCUM) {
            float4 o0 = *(float4*)op, o1 = *(float4*)(op + 4);
            o0.x += v0.x; o0.y += v0.y; o0.z += v1.x; o0.w += v1.y;
            o1.x += v2.x; o1.y += v2.y; o1.z += v3.x; o1.w += v3.y;
            *(float4*)op = o0; *(float4*)(op + 4) = o1;
        } else {
            *(float4*)op       = make_float4(v0.x, v0.y, v1.x, v1.y);
            *(float4*)(op + 4) = make_float4(v2.x, v2.y, v3.x, v3.y);
        }
    }
}

// ---------------------------------------------------------------------------
extern "C" void kernel_launch(void* const* d_in, const int* in_sizes, int n_in,
                              void* d_out, int out_size) {
    const float* feat   = (const float*)d_in[0];
    const float* gamma1 = (const float*)d_in[1];
    const float* beta1  = (const float*)d_in[2];
    const float* W1     = (const float*)d_in[3];
    const float* gamma2 = (const float*)d_in[4];
    const float* beta2  = (const float*)d_in[5];
    const float* W2     = (const float*)d_in[6];
    const float* Wnin   = (const float*)d_in[7];
    const int*   nbr    = (const int*)d_in[8];
    const void*  mask   = d_in[9];
    float*       out    = (float*)d_out;

    const int N = in_sizes[0] / AA;

    float *p_out1, *p_s1, *p_b1, *p_s2, *p_b2;
    cudaGetSymbolAddress((void**)&p_out1, g_out1);
    cudaGetSymbolAddress((void**)&p_s1,   g_scale1);
    cudaGetSymbolAddress((void**)&p_b1,   g_bias1);
    cudaGetSymbolAddress((void**)&p_s2,   g_scale2);
    cudaGetSymbolAddress((void**)&p_b2,   g_bias2);

    const int gtiles = (N + 127) / 128;

    // mask layout detect + counter reset
    k_detect<<<1, 256>>>((const unsigned char*)mask);

    // BN1 stats -> folded affine
    k_stats<AA, 4><<<PB, dim3(AA, 4)>>>(feat, N);
    k_fin<AA><<<1, AA>>>(gamma1, beta1, p_s1, p_b1, N);

    // rulebook
    k_rule<<<(N + 255) / 256, 256>>>(mask, N);

    // conv1 accumulator zero
    size_t n4 = (size_t)N * BBC / 4;
    k_zero<<<(int)((n4 + 255) / 256), 256>>>(p_out1, n4);

    // NiN shortcut: out = feat @ Wnin  (initializes d_out)
    k_gemm<AA, false, false, false><<<gtiles, 256>>>(
        feat, Wnin, out, nullptr, 0, nullptr, nullptr, N);

    // conv1: out1 += bnrelu1(feat)[nbr[:,k]] @ W1[k]  (masked rows only)
    for (int k = 0; k < KK; k++)
        k_gemm<AA, true, true, true><<<gtiles, 256>>>(
            feat, W1 + (size_t)k * AA * BBC, p_out1, nbr, k, p_s1, p_b1, N);

    // BN2 stats -> folded affine
    k_stats<BBC, 2><<<PB, dim3(BBC, 2)>>>(p_out1, N);
    k_fin<BBC><<<1, BBC>>>(gamma2, beta2, p_s2, p_b2, N);

    // conv2: out += bnrelu2(out1)[nbr[:,k]] @ W2[k]
    for (int k = 0; k < KK; k++)
        k_gemm<BBC, true, true, true><<<gtiles, 256>>>(
            p_out1, W2 + (size_t)k * BBC * BBC, out, nbr, k, p_s2, p_b2, N);
}

// round 3
// speedup vs baseline: 1.6645x; 1.6645x over previous
#include <cuda_runtime.h>
#include <cuda_bf16.h>
#include <cstdint>

// ---------------------------------------------------------------------------
// ResidualBlock: y = feat@Wnin + subconv(bnrelu2(subconv(bnrelu1(feat),W1)),W2)
// N=100000, A=64, B=128, K=27. fp32 in/out.
// Engine: baseline mma.sync m16n8k16 bf16 (HMMA) with 3-term hi/lo split.
// Structure: rulebook-compacted per-offset gather-GEMM passes (round-1 proven).
// ---------------------------------------------------------------------------

#define KK   27
#define AA   64
#define BB   128
#define NMAX 100000
#define PB   132

// ---------------- static device scratch ------------------------------------
__device__ float g_out1[(size_t)NMAX * BB];                 // conv1 out (fp32)
__device__ int   g_idx[KK * NMAX];                          // rulebook lists
__device__ int   g_cnt[KK];
__device__ int   g_mask_u8;
__device__ float g_ps[PB * BB], g_pq[PB * BB];
__device__ float g_s1[AA], g_b1[AA], g_s2[BB], g_b2[BB];
// packed weights: per (k, chunk): [hi plane 2560 u32][lo plane 2560 u32]
// plane layout: n*20 + slot(p), p = k-pair index 0..15
__device__ __align__(16) uint32_t g_W1p[KK * 2 * 2 * 2560];
__device__ __align__(16) uint32_t g_W2p[KK * 4 * 2 * 2560];
__device__ __align__(16) uint32_t g_Wnp[2 * 2 * 2560];

// pair p (0..15) -> interleaved slot so fragment reg pairs are adjacent
__host__ __device__ __forceinline__ int pslot(int p) {
    return (p >> 3) * 8 + ((p & 3) * 2) + ((p & 7) >> 2);
}

// pack two fp32 -> bf16x2 (low half = first arg)
__device__ __forceinline__ uint32_t cvt2(float lo, float hi) {
    uint32_t r;
    asm("cvt.rn.bf16x2.f32 %0, %1, %2;" : "=r"(r) : "f"(hi), "f"(lo));
    return r;
}

// mma.sync m16n8k16 bf16: a={aL.x,aH.x,aL.y,aH.y}, b={b.x,b.y}, d += a@b
__device__ __forceinline__ void mma_bf(float* d, uint2 aL, uint2 aH, uint2 b) {
    asm volatile(
        "mma.sync.aligned.m16n8k16.row.col.f32.bf16.bf16.f32 "
        "{%0,%1,%2,%3}, {%4,%5,%6,%7}, {%8,%9}, {%0,%1,%2,%3};"
        : "+f"(d[0]), "+f"(d[1]), "+f"(d[2]), "+f"(d[3])
        : "r"(aL.x), "r"(aH.x), "r"(aL.y), "r"(aH.y), "r"(b.x), "r"(b.y));
}

// ---------------- small kernels --------------------------------------------
__global__ void k_detect(const unsigned char* __restrict__ m8) {
    int t = threadIdx.x;
    if (t < KK) g_cnt[t] = 0;
    int ok = (m8[t * KK + KK / 2] != 0) ? 1 : 0;
    int all = __syncthreads_and(ok);
    if (t == 0) g_mask_u8 = all;
}

template <int CH, int RG>
__global__ void k_stats(const float* __restrict__ x, int N) {
    int c = threadIdx.x, r = threadIdx.y;
    float s = 0.f, q = 0.f;
    for (int i = blockIdx.x * RG + r; i < N; i += gridDim.x * RG) {
        float v = x[(size_t)i * CH + c];
        s += v; q += v * v;
    }
    __shared__ float sh[RG][CH];
    __shared__ float shq[RG][CH];
    sh[r][c] = s; shq[r][c] = q;
    __syncthreads();
    if (r == 0) {
#pragma unroll
        for (int j = 1; j < RG; j++) { s += sh[j][c]; q += shq[j][c]; }
        g_ps[blockIdx.x * CH + c] = s;
        g_pq[blockIdx.x * CH + c] = q;
    }
}

template <int CH>
__global__ void k_fin(const float* __restrict__ gamma,
                      const float* __restrict__ beta,
                      float* __restrict__ scl, float* __restrict__ bia, int N) {
    int c = threadIdx.x;
    float s = 0.f, q = 0.f;
    for (int b = 0; b < PB; b++) { s += g_ps[b * CH + c]; q += g_pq[b * CH + c]; }
    float mu  = s / (float)N;
    float var = q / (float)N - mu * mu;
    if (var < 0.f) var = 0.f;
    float rs = rsqrtf(var + 1e-4f);
    float sc = gamma[c] * rs;
    scl[c] = sc;
    bia[c] = beta[c] - mu * sc;
}

__global__ void k_rule(const void* __restrict__ mp, int N) {
    int i = blockIdx.x * blockDim.x + threadIdx.x;
    if (i >= N) return;
    const bool u8 = (g_mask_u8 != 0);
    const unsigned char* m8  = (const unsigned char*)mp;
    const int*           m32 = (const int*)mp;
#pragma unroll
    for (int k = 0; k < KK; k++) {
        bool m = u8 ? (m8[(size_t)i * KK + k] != 0)
                    : (m32[(size_t)i * KK + k] != 0);
        if (m) {
            int p = atomicAdd(&g_cnt[k], 1);
            g_idx[k * N + p] = i;
        }
    }
}

__global__ void k_zero(float* __restrict__ p, size_t n4) {
    size_t i = blockIdx.x * (size_t)blockDim.x + threadIdx.x;
    if (i < n4) ((float4*)p)[i] = make_float4(0.f, 0.f, 0.f, 0.f);
}

// weight pack: transpose-to-[n][k], bf16 hi/lo split, fragment-slot layout
__global__ void k_wcvt(const float* __restrict__ W1, const float* __restrict__ W2,
                       const float* __restrict__ Wn) {
    const int T1 = KK * 2 * 128 * 16;          // 110592
    const int T2 = T1 + KK * 4 * 128 * 16;     // +221184
    const int T3 = T2 + 2 * 128 * 16;          // +4096
    int idx = blockIdx.x * blockDim.x + threadIdx.x;
    if (idx >= T3) return;
    const float* src; uint32_t* dst; int n, p;
    if (idx < T1) {
        int k = idx / (2 * 128 * 16), r = idx % (2 * 128 * 16);
        int ch = r / (128 * 16), r2 = r % (128 * 16);
        n = r2 / 16; p = r2 % 16;
        src = W1 + (size_t)k * 64 * 128 + (size_t)(ch * 32 + 2 * p) * 128 + n;
        dst = g_W1p + ((size_t)(k * 2 + ch) * 2) * 2560;
    } else if (idx < T2) {
        int i2 = idx - T1;
        int k = i2 / (4 * 128 * 16), r = i2 % (4 * 128 * 16);
        int ch = r / (128 * 16), r2 = r % (128 * 16);
        n = r2 / 16; p = r2 % 16;
        src = W2 + (size_t)k * 128 * 128 + (size_t)(ch * 32 + 2 * p) * 128 + n;
        dst = g_W2p + ((size_t)(k * 4 + ch) * 2) * 2560;
    } else {
        int i2 = idx - T2;
        int ch = i2 / (128 * 16), r2 = i2 % (128 * 16);
        n = r2 / 16; p = r2 % 16;
        src = Wn + (size_t)(ch * 32 + 2 * p) * 128 + n;
        dst = g_Wnp + ((size_t)ch * 2) * 2560;
    }
    float w0 = src[0], w1 = src[128];
    __nv_bfloat16 h0 = __float2bfloat16(w0);
    __nv_bfloat16 h1 = __float2bfloat16(w1);
    float l0 = w0 - __bfloat162float(h0);
    float l1 = w1 - __bfloat162float(h1);
    uint32_t hp = ((uint32_t)*(unsigned short*)&h1 << 16) |
                  (uint32_t)*(unsigned short*)&h0;
    int off = n * 20 + pslot(p);
    dst[off] = hp;
    __nv_bfloat16 g0 = __float2bfloat16(l0);
    __nv_bfloat16 g1 = __float2bfloat16(l1);
    uint32_t lp = ((uint32_t)*(unsigned short*)&g1 << 16) |
                  (uint32_t)*(unsigned short*)&g0;
    dst[2560 + off] = lp;
}

// ---------------- gather-GEMM pass (HMMA bf16 3-term split) -----------------
// Block: 128 compacted sites x 128 cols. 8 warps (4x2), warp tile 32x64.
// K handled in 32-chunks: gather A + affine/relu + hi/lo split -> smem,
// W chunk linear-copied (pre-packed). Out accum in fp32 regs; RMW epilogue.
template <int CIN, bool GATHER, bool AFFINE, bool ACCUM>
__global__ void __launch_bounds__(256, 2) k_pass(
    const float* __restrict__ src, const uint32_t* __restrict__ Wp,
    float* __restrict__ out, const int* __restrict__ nbr, int k,
    const float* __restrict__ scl, const float* __restrict__ bia, int N) {

    const int cnt  = GATHER ? g_cnt[k] : N;
    const int tile = blockIdx.x * 128;
    if (tile >= cnt) return;

    constexpr int NCH = CIN / 32;

    __shared__ __align__(16) uint32_t Ah[128 * 20];
    __shared__ __align__(16) uint32_t Al[128 * 20];
    __shared__ __align__(16) uint32_t Bhl[2 * 2560];   // hi plane then lo plane
    __shared__ int   s_src[128];
    __shared__ int   s_dst[128];
    __shared__ float s_s[CIN], s_b[CIN];

    const int tid  = threadIdx.x;
    const int wid  = tid >> 5, lane = tid & 31;
    const int qr = lane >> 2, qc = lane & 3;
    const int wm = wid >> 1, wn = wid & 1;

    if (tid < 128) {
        int gr = tile + tid;
        int i = -1, sr = -1;
        if (gr < cnt) {
            i  = GATHER ? g_idx[k * N + gr] : gr;
            sr = GATHER ? nbr[(size_t)i * KK + k] : i;
        }
        s_dst[tid] = i;
        s_src[tid] = sr;
    }
    if (AFFINE) {
        for (int c = tid; c < CIN; c += 256) { s_s[c] = scl[c]; s_b[c] = bia[c]; }
    }
    __syncthreads();

    float acc[2][8][4];
#pragma unroll
    for (int a = 0; a < 2; a++)
#pragma unroll
        for (int b = 0; b < 8; b++)
#pragma unroll
            for (int c = 0; c < 4; c++) acc[a][b][c] = 0.f;

    const int r = tid >> 1, h = tid & 1;
    const int sr = s_src[r];

    for (int ch = 0; ch < NCH; ch++) {
        if (ch > 0) __syncthreads();           // protect smem from prev mma reads

        // ---- B fill: linear copy of packed hi+lo planes (5120 u32)
        {
            const uint4* ws = (const uint4*)(Wp + (size_t)(ch * 2) * 2560);
            uint4*       bd = (uint4*)Bhl;
#pragma unroll
            for (int j = 0; j < 5; j++) bd[tid + j * 256] = ws[tid + j * 256];
        }
        // ---- A fill: gather 16 floats/thread, affine+relu, split, slot store
        {
            const float4* rp =
                (const float4*)(src + (size_t)sr * CIN + ch * 32 + h * 16);
            const uint32_t abase = (uint32_t)r * 20u + (uint32_t)h * 8u;
            const int cb = ch * 32 + h * 16;
#pragma unroll
            for (int j = 0; j < 4; j++) {
                float4 v = make_float4(0.f, 0.f, 0.f, 0.f);
                if (sr >= 0) v = rp[j];
                if (AFFINE) {
                    int c = cb + j * 4;
                    v.x = fmaxf(fmaf(v.x, s_s[c],     s_b[c]),     0.f);
                    v.y = fmaxf(fmaf(v.y, s_s[c + 1], s_b[c + 1]), 0.f);
                    v.z = fmaxf(fmaf(v.z, s_s[c + 2], s_b[c + 2]), 0.f);
                    v.w = fmaxf(fmaf(v.w, s_s[c + 3], s_b[c + 3]), 0.f);
                }
                uint32_t p0 = cvt2(v.x, v.y);
                uint32_t p1 = cvt2(v.z, v.w);
                float rx = v.x - __uint_as_float(p0 << 16);
                float ry = v.y - __uint_as_float(p0 & 0xffff0000u);
                float rz = v.z - __uint_as_float(p1 << 16);
                float rw = v.w - __uint_as_float(p1 & 0xffff0000u);
                uint32_t q0 = cvt2(rx, ry);
                uint32_t q1 = cvt2(rz, rw);
                const int s0 = pslot(h * 8 + j * 2) - h * 8;      // local slots
                const int s1 = pslot(h * 8 + j * 2 + 1) - h * 8;
                Ah[abase + s0] = p0;  Ah[abase + s1] = p1;
                Al[abase + s0] = q0;  Al[abase + s1] = q1;
            }
        }
        __syncthreads();

        // ---- MMA: 2 k16 steps x 3 split terms x (2 M-tiles x 8 N-tiles)
#pragma unroll
        for (int g = 0; g < 2; g++) {
            uint2 ah[2][2], al[2][2], bf[8];
#pragma unroll
            for (int mt = 0; mt < 2; mt++) {
                int r0 = wm * 32 + mt * 16 + qr;
                int o0 = r0 * 20 + g * 8 + qc * 2;
                int o1 = (r0 + 8) * 20 + g * 8 + qc * 2;
                ah[mt][0] = *(const uint2*)&Ah[o0];
                ah[mt][1] = *(const uint2*)&Ah[o1];
                al[mt][0] = *(const uint2*)&Al[o0];
                al[mt][1] = *(const uint2*)&Al[o1];
            }
#pragma unroll
            for (int nt = 0; nt < 8; nt++) {
                int c0 = wn * 64 + nt * 8 + qr;
                bf[nt] = *(const uint2*)&Bhl[c0 * 20 + g * 8 + qc * 2];
            }
#pragma unroll
            for (int mt = 0; mt < 2; mt++)
#pragma unroll
                for (int nt = 0; nt < 8; nt++)
                    mma_bf(acc[mt][nt], ah[mt][0], ah[mt][1], bf[nt]);  // hi*hi
#pragma unroll
            for (int mt = 0; mt < 2; mt++)
#pragma unroll
                for (int nt = 0; nt < 8; nt++)
                    mma_bf(acc[mt][nt], al[mt][0], al[mt][1], bf[nt]);  // lo*hi
#pragma unroll
            for (int nt = 0; nt < 8; nt++) {
                int c0 = wn * 64 + nt * 8 + qr;
                bf[nt] = *(const uint2*)&Bhl[2560 + c0 * 20 + g * 8 + qc * 2];
            }
#pragma unroll
            for (int mt = 0; mt < 2; mt++)
#pragma unroll
                for (int nt = 0; nt < 8; nt++)
                    mma_bf(acc[mt][nt], ah[mt][0], ah[mt][1], bf[nt]);  // hi*lo
        }
    }

    // ---- epilogue: fp32 accum -> gmem (RMW if ACCUM), rows unique per pass
#pragma unroll
    for (int mt = 0; mt < 2; mt++) {
        int r0 = wm * 32 + mt * 16 + qr;
        int dA = s_dst[r0], dB = s_dst[r0 + 8];
#pragma unroll
        for (int nt = 0; nt < 8; nt++) {
            int col = wn * 64 + nt * 8 + qc * 2;
            if (dA >= 0) {
                float2* p = (float2*)(out + (size_t)dA * BB + col);
                if (ACCUM) {
                    float2 v = *p;
                    v.x += acc[mt][nt][0]; v.y += acc[mt][nt][1];
                    *p = v;
                } else {
                    *p = make_float2(acc[mt][nt][0], acc[mt][nt][1]);
                }
            }
            if (dB >= 0) {
                float2* p = (float2*)(out + (size_t)dB * BB + col);
                if (ACCUM) {
                    float2 v = *p;
                    v.x += acc[mt][nt][2]; v.y += acc[mt][nt][3];
                    *p = v;
                } else {
                    *p = make_float2(acc[mt][nt][2], acc[mt][nt][3]);
                }
            }
        }
    }
}

// ---------------------------------------------------------------------------
extern "C" void kernel_launch(void* const* d_in, const int* in_sizes, int n_in,
                              void* d_out, int out_size) {
    const float* feat   = (const float*)d_in[0];
    const float* gamma1 = (const float*)d_in[1];
    const float* beta1  = (const float*)d_in[2];
    const float* W1     = (const float*)d_in[3];
    const float* gamma2 = (const float*)d_in[4];
    const float* beta2  = (const float*)d_in[5];
    const float* W2     = (const float*)d_in[6];
    const float* Wnin   = (const float*)d_in[7];
    const int*   nbr    = (const int*)d_in[8];
    const void*  mask   = d_in[9];
    float*       out    = (float*)d_out;

    const int N = in_sizes[0] / AA;

    float *p_out1, *p_s1, *p_b1, *p_s2, *p_b2;
    uint32_t *p_W1p, *p_W2p, *p_Wnp;
    cudaGetSymbolAddress((void**)&p_out1, g_out1);
    cudaGetSymbolAddress((void**)&p_s1,   g_s1);
    cudaGetSymbolAddress((void**)&p_b1,   g_b1);
    cudaGetSymbolAddress((void**)&p_s2,   g_s2);
    cudaGetSymbolAddress((void**)&p_b2,   g_b2);
    cudaGetSymbolAddress((void**)&p_W1p,  g_W1p);
    cudaGetSymbolAddress((void**)&p_W2p,  g_W2p);
    cudaGetSymbolAddress((void**)&p_Wnp,  g_Wnp);

    const int gtiles = (N + 127) / 128;
    const int wtot   = KK * 2 * 128 * 16 + KK * 4 * 128 * 16 + 2 * 128 * 16;

    // mask dtype detect + rulebook counter reset
    k_detect<<<1, 256>>>((const unsigned char*)mask);

    // weight pack
    k_wcvt<<<(wtot + 255) / 256, 256>>>(W1, W2, Wnin);

    // BN1 folded affine
    k_stats<AA, 4><<<PB, dim3(AA, 4)>>>(feat, N);
    k_fin<AA><<<1, AA>>>(gamma1, beta1, p_s1, p_b1, N);

    // rulebook
    k_rule<<<(N + 255) / 256, 256>>>(mask, N);

    // conv1 accumulator zero
    size_t n4 = (size_t)N * BB / 4;
    k_zero<<<(int)((n4 + 255) / 256), 256>>>(p_out1, n4);

    // NiN shortcut: out = feat @ Wnin (initializes d_out)
    k_pass<AA, false, false, false><<<gtiles, 256>>>(
        feat, p_Wnp, out, nullptr, 0, nullptr, nullptr, N);

    // conv1: out1 += bnrelu1(feat)[rule k] @ W1[k]
    for (int k = 0; k < KK; k++)
        k_pass<AA, true, true, true><<<gtiles, 256>>>(
            feat, p_W1p + (size_t)k * 2 * 2 * 2560, p_out1, nbr, k, p_s1, p_b1, N);

    // BN2 folded affine
    k_stats<BB, 2><<<PB, dim3(BB, 2)>>>(p_out1, N);
    k_fin<BB><<<1, BB>>>(gamma2, beta2, p_s2, p_b2, N);

    // conv2: out += bnrelu2(out1)[rule k] @ W2[k]
    for (int k = 0; k < KK; k++)
        k_pass<BB, true, true, true><<<gtiles, 256>>>(
            p_out1, p_W2p + (size_t)k * 4 * 2 * 2560, out, nbr, k, p_s2, p_b2, N);
}

// round 7
// speedup vs baseline: 2.1853x; 1.3129x over previous
#include <cuda_runtime.h>
#include <cuda_bf16.h>
#include <cstdint>

// ---------------------------------------------------------------------------
// ResidualBlock: y = feat@Wnin + subconv(bnrelu2(subconv(bnrelu1(feat),W1)),W2)
// N=100000, A=64, B=128, K=27. fp32 in/out.
// Engine: mma.sync m16n8k16 bf16 (HMMA), 3-term hi/lo split, fp32 accum.
// Structure: fused output-stationary conv kernels, linear weight walk.
// FIX vs round 6: masked-off rows contribute TRUE zeros (affine applied only
// to valid gathered rows) — reference masks POST-bnrelu features.
// ---------------------------------------------------------------------------

#define KK   27
#define AA   64
#define BB   128
#define NMAX 100000
#define PB   132

// ---------------- static device scratch ------------------------------------
__device__ float g_out1[(size_t)NMAX * BB];                 // conv1 out (fp32)
__device__ int   g_gidx[KK * NMAX];                         // gather idx or -1
__device__ int   g_mask_u8;
__device__ float g_ps[PB * BB], g_pq[PB * BB];
__device__ float g_s1[AA], g_b1[AA], g_s2[BB], g_b2[BB];
// packed weights per (k, chunk): [hi plane 2560 u32][lo plane 2560 u32]
// plane layout: n*20 + slot(p), p = k-pair index 0..15. Stage-linear order.
__device__ __align__(16) uint32_t g_W1p[KK * 2 * 2 * 2560];
__device__ __align__(16) uint32_t g_W2p[KK * 4 * 2 * 2560];
__device__ __align__(16) uint32_t g_Wnp[2 * 2 * 2560];

// pair p (0..15) -> interleaved slot so fragment reg pairs are adjacent
__host__ __device__ __forceinline__ int pslot(int p) {
    return (p >> 3) * 8 + ((p & 3) * 2) + ((p & 7) >> 2);
}

// pack two fp32 -> bf16x2 (low half = first arg)
__device__ __forceinline__ uint32_t cvt2(float lo, float hi) {
    uint32_t r;
    asm("cvt.rn.bf16x2.f32 %0, %1, %2;" : "=r"(r) : "f"(hi), "f"(lo));
    return r;
}

// mma.sync m16n8k16 bf16: a={aL.x,aH.x,aL.y,aH.y}, b={b.x,b.y}, d += a@b
__device__ __forceinline__ void mma_bf(float* d, uint2 aL, uint2 aH, uint2 b) {
    asm volatile(
        "mma.sync.aligned.m16n8k16.row.col.f32.bf16.bf16.f32 "
        "{%0,%1,%2,%3}, {%4,%5,%6,%7}, {%8,%9}, {%0,%1,%2,%3};"
        : "+f"(d[0]), "+f"(d[1]), "+f"(d[2]), "+f"(d[3])
        : "r"(aL.x), "r"(aH.x), "r"(aL.y), "r"(aH.y), "r"(b.x), "r"(b.y));
}

// ---------------- small kernels --------------------------------------------
__global__ void k_detect(const unsigned char* __restrict__ m8) {
    int t = threadIdx.x;
    int ok = (m8[t * KK + KK / 2] != 0) ? 1 : 0;
    int all = __syncthreads_and(ok);
    if (t == 0) g_mask_u8 = all;
}

// precompute gather index per (k, site): masked neighbor or -1
__global__ void k_gidx(const int* __restrict__ nbr,
                       const void* __restrict__ mp, int N) {
    int i = blockIdx.x * blockDim.x + threadIdx.x;
    if (i >= N) return;
    const bool u8 = (g_mask_u8 != 0);
    const unsigned char* m8  = (const unsigned char*)mp;
    const int*           m32 = (const int*)mp;
#pragma unroll
    for (int k = 0; k < KK; k++) {
        bool m = u8 ? (m8[(size_t)i * KK + k] != 0)
                    : (m32[(size_t)i * KK + k] != 0);
        g_gidx[k * N + i] = m ? nbr[(size_t)i * KK + k] : -1;
    }
}

template <int CH, int RG>
__global__ void k_stats(const float* __restrict__ x, int N) {
    int c = threadIdx.x, r = threadIdx.y;
    float s = 0.f, q = 0.f;
    for (int i = blockIdx.x * RG + r; i < N; i += gridDim.x * RG) {
        float v = x[(size_t)i * CH + c];
        s += v; q += v * v;
    }
    __shared__ float sh[RG][CH];
    __shared__ float shq[RG][CH];
    sh[r][c] = s; shq[r][c] = q;
    __syncthreads();
    if (r == 0) {
#pragma unroll
        for (int j = 1; j < RG; j++) { s += sh[j][c]; q += shq[j][c]; }
        g_ps[blockIdx.x * CH + c] = s;
        g_pq[blockIdx.x * CH + c] = q;
    }
}

template <int CH>
__global__ void k_fin(const float* __restrict__ gamma,
                      const float* __restrict__ beta,
                      float* __restrict__ scl, float* __restrict__ bia, int N) {
    int c = threadIdx.x;
    float s = 0.f, q = 0.f;
    for (int b = 0; b < PB; b++) { s += g_ps[b * CH + c]; q += g_pq[b * CH + c]; }
    float mu  = s / (float)N;
    float var = q / (float)N - mu * mu;
    if (var < 0.f) var = 0.f;
    float rs = rsqrtf(var + 1e-4f);
    float sc = gamma[c] * rs;
    scl[c] = sc;
    bia[c] = beta[c] - mu * sc;
}

// weight pack: transpose-to-[n][k], bf16 hi/lo split, fragment-slot layout
__global__ void k_wcvt(const float* __restrict__ W1, const float* __restrict__ W2,
                       const float* __restrict__ Wn) {
    const int T1 = KK * 2 * 128 * 16;
    const int T2 = T1 + KK * 4 * 128 * 16;
    const int T3 = T2 + 2 * 128 * 16;
    int idx = blockIdx.x * blockDim.x + threadIdx.x;
    if (idx >= T3) return;
    const float* src; uint32_t* dst; int n, p;
    if (idx < T1) {
        int k = idx / (2 * 128 * 16), r = idx % (2 * 128 * 16);
        int ch = r / (128 * 16), r2 = r % (128 * 16);
        n = r2 / 16; p = r2 % 16;
        src = W1 + (size_t)k * 64 * 128 + (size_t)(ch * 32 + 2 * p) * 128 + n;
        dst = g_W1p + ((size_t)(k * 2 + ch) * 2) * 2560;
    } else if (idx < T2) {
        int i2 = idx - T1;
        int k = i2 / (4 * 128 * 16), r = i2 % (4 * 128 * 16);
        int ch = r / (128 * 16), r2 = r % (128 * 16);
        n = r2 / 16; p = r2 % 16;
        src = W2 + (size_t)k * 128 * 128 + (size_t)(ch * 32 + 2 * p) * 128 + n;
        dst = g_W2p + ((size_t)(k * 4 + ch) * 2) * 2560;
    } else {
        int i2 = idx - T2;
        int ch = i2 / (128 * 16), r2 = i2 % (128 * 16);
        n = r2 / 16; p = r2 % 16;
        src = Wn + (size_t)(ch * 32 + 2 * p) * 128 + n;
        dst = g_Wnp + ((size_t)ch * 2) * 2560;
    }
    float w0 = src[0], w1 = src[128];
    __nv_bfloat16 h0 = __float2bfloat16(w0);
    __nv_bfloat16 h1 = __float2bfloat16(w1);
    float l0 = w0 - __bfloat162float(h0);
    float l1 = w1 - __bfloat162float(h1);
    uint32_t hp = ((uint32_t)*(unsigned short*)&h1 << 16) |
                  (uint32_t)*(unsigned short*)&h0;
    int off = n * 20 + pslot(p);
    dst[off] = hp;
    __nv_bfloat16 e0 = __float2bfloat16(l0);
    __nv_bfloat16 e1 = __float2bfloat16(l1);
    uint32_t lp = ((uint32_t)*(unsigned short*)&e1 << 16) |
                  (uint32_t)*(unsigned short*)&e0;
    dst[2560 + off] = lp;
}

// ---------------- fused output-stationary conv kernel ------------------------
// MODE 0: out  = feat @ Wnin          (2 stages, dense, no affine, store)
// MODE 1: out1 = sum_k bnrelu1(feat)[gidx] @ W1[k]   (54 stages, store)
// MODE 2: out += sum_k bnrelu2(out1)[gidx] @ W2[k]   (108 stages, RMW add)
// Block: 128 sites x 128 cols, D in fp32 regs; 8 warps (4M x 2N).
// Stage s: k = s/NCH, chunk = s%NCH; weights consumed LINEARLY (bp = s*5120).
// Masked-off rows (sr < 0) contribute TRUE zeros (no affine applied).

template <int CIN, int MODE>
__global__ void __launch_bounds__(256) k_conv(
    const float* __restrict__ src, float* __restrict__ outp, int N) {

    constexpr int NCH = CIN / 32;
    constexpr int NK  = (MODE == 0) ? 1 : KK;
    constexpr int S   = NK * NCH;

    __shared__ __align__(16) uint32_t Ah[128 * 20];
    __shared__ __align__(16) uint32_t Al[128 * 20];
    __shared__ __align__(16) uint32_t Bs[2 * 2560];
    __shared__ float s_s[CIN], s_b[CIN];

    const uint32_t* Wb = (MODE == 0) ? g_Wnp : (MODE == 1 ? g_W1p : g_W2p);

    const int tid = threadIdx.x;
    const int wid = tid >> 5, lane = tid & 31;
    const int qr = lane >> 2, qc = lane & 3;
    const int wm = wid >> 1, wn = wid & 1;
    const int tile = blockIdx.x * 128;
    const int r = tid >> 1, h = tid & 1;
    const int site = tile + r;

    if (MODE != 0) {
        for (int c = tid; c < CIN; c += 256) {
            s_s[c] = (MODE == 1) ? g_s1[c] : g_s2[c];
            s_b[c] = (MODE == 1) ? g_b1[c] : g_b2[c];
        }
    }

    float acc[2][8][4];
#pragma unroll
    for (int a = 0; a < 2; a++)
#pragma unroll
        for (int b = 0; b < 8; b++)
#pragma unroll
            for (int c = 0; c < 4; c++) acc[a][b][c] = 0.f;

    for (int s = 0; s < S; s++) {
        const int k  = s / NCH;
        const int c0 = (s % NCH) * 32;

        __syncthreads();               // MMA(s-1) done; s=0: s_s/s_b ready

        // ---- B fill: linear copy of packed hi+lo planes (5120 u32)
        {
            const uint4* ws = (const uint4*)(Wb + (size_t)s * 5120);
            uint4*       bd = (uint4*)Bs;
#pragma unroll
            for (int j = 0; j < 5; j++) bd[tid + j * 256] = ws[tid + j * 256];
        }
        // ---- A fill: gather + affine/relu + hi/lo split.
        // CRITICAL: affine applies ONLY to valid rows; masked rows are zeros
        // (reference: g = where(mask, bnrelu(f)[nbr], 0)).
        {
            int sr;
            if (MODE == 0) sr = (site < N) ? site : -1;
            else           sr = (site < N) ? g_gidx[(size_t)k * N + site] : -1;
            const float4* rp =
                (const float4*)(src + (size_t)sr * CIN + c0 + h * 16);
            const uint32_t abase = (uint32_t)r * 20u + (uint32_t)h * 8u;
            const int cb = c0 + h * 16;
#pragma unroll
            for (int j = 0; j < 4; j++) {
                float4 v = make_float4(0.f, 0.f, 0.f, 0.f);
                if (sr >= 0) {
                    v = rp[j];
                    if (MODE != 0) {
                        int c = cb + j * 4;
                        v.x = fmaxf(fmaf(v.x, s_s[c],     s_b[c]),     0.f);
                        v.y = fmaxf(fmaf(v.y, s_s[c + 1], s_b[c + 1]), 0.f);
                        v.z = fmaxf(fmaf(v.z, s_s[c + 2], s_b[c + 2]), 0.f);
                        v.w = fmaxf(fmaf(v.w, s_s[c + 3], s_b[c + 3]), 0.f);
                    }
                }
                uint32_t p0 = cvt2(v.x, v.y);
                uint32_t p1 = cvt2(v.z, v.w);
                float rx = v.x - __uint_as_float(p0 << 16);
                float ry = v.y - __uint_as_float(p0 & 0xffff0000u);
                float rz = v.z - __uint_as_float(p1 << 16);
                float rw = v.w - __uint_as_float(p1 & 0xffff0000u);
                uint32_t q0 = cvt2(rx, ry);
                uint32_t q1 = cvt2(rz, rw);
                const int s0 = pslot(h * 8 + j * 2) - h * 8;
                const int s1 = pslot(h * 8 + j * 2 + 1) - h * 8;
                Ah[abase + s0] = p0;  Ah[abase + s1] = p1;
                Al[abase + s0] = q0;  Al[abase + s1] = q1;
            }
        }
        __syncthreads();               // fills visible

        // ---- MMA: 2 k16 steps x 3 split terms x (2 M x 8 N tiles)
#pragma unroll
        for (int g = 0; g < 2; g++) {
            uint2 ah[2][2], al[2][2], bf[8];
#pragma unroll
            for (int mt = 0; mt < 2; mt++) {
                int r0 = wm * 32 + mt * 16 + qr;
                int o0 = r0 * 20 + g * 8 + qc * 2;
                int o1 = (r0 + 8) * 20 + g * 8 + qc * 2;
                ah[mt][0] = *(const uint2*)&Ah[o0];
                ah[mt][1] = *(const uint2*)&Ah[o1];
                al[mt][0] = *(const uint2*)&Al[o0];
                al[mt][1] = *(const uint2*)&Al[o1];
            }
#pragma unroll
            for (int nt = 0; nt < 8; nt++) {
                int c0b = wn * 64 + nt * 8 + qr;
                bf[nt] = *(const uint2*)&Bs[c0b * 20 + g * 8 + qc * 2];
            }
#pragma unroll
            for (int mt = 0; mt < 2; mt++)
#pragma unroll
                for (int nt = 0; nt < 8; nt++)
                    mma_bf(acc[mt][nt], ah[mt][0], ah[mt][1], bf[nt]);  // hi*hi
#pragma unroll
            for (int mt = 0; mt < 2; mt++)
#pragma unroll
                for (int nt = 0; nt < 8; nt++)
                    mma_bf(acc[mt][nt], al[mt][0], al[mt][1], bf[nt]);  // lo*hi
#pragma unroll
            for (int nt = 0; nt < 8; nt++) {
                int c0b = wn * 64 + nt * 8 + qr;
                bf[nt] = *(const uint2*)&Bs[2560 + c0b * 20 + g * 8 + qc * 2];
            }
#pragma unroll
            for (int mt = 0; mt < 2; mt++)
#pragma unroll
                for (int nt = 0; nt < 8; nt++)
                    mma_bf(acc[mt][nt], ah[mt][0], ah[mt][1], bf[nt]);  // hi*lo
        }
    }

    // ---- epilogue: store (MODE 0/1) or RMW add (MODE 2)
#pragma unroll
    for (int mt = 0; mt < 2; mt++) {
        int r0 = wm * 32 + mt * 16 + qr;
        int sA = tile + r0, sB = tile + r0 + 8;
#pragma unroll
        for (int nt = 0; nt < 8; nt++) {
            int col = wn * 64 + nt * 8 + qc * 2;
            if (sA < N) {
                float2* p = (float2*)(outp + (size_t)sA * BB + col);
                if (MODE == 2) {
                    float2 v = *p;
                    v.x += acc[mt][nt][0]; v.y += acc[mt][nt][1];
                    *p = v;
                } else {
                    *p = make_float2(acc[mt][nt][0], acc[mt][nt][1]);
                }
            }
            if (sB < N) {
                float2* p = (float2*)(outp + (size_t)sB * BB + col);
                if (MODE == 2) {
                    float2 v = *p;
                    v.x += acc[mt][nt][2]; v.y += acc[mt][nt][3];
                    *p = v;
                } else {
                    *p = make_float2(acc[mt][nt][2], acc[mt][nt][3]);
                }
            }
        }
    }
}

// ---------------------------------------------------------------------------
extern "C" void kernel_launch(void* const* d_in, const int* in_sizes, int n_in,
                              void* d_out, int out_size) {
    const float* feat   = (const float*)d_in[0];
    const float* gamma1 = (const float*)d_in[1];
    const float* beta1  = (const float*)d_in[2];
    const float* W1     = (const float*)d_in[3];
    const float* gamma2 = (const float*)d_in[4];
    const float* beta2  = (const float*)d_in[5];
    const float* W2     = (const float*)d_in[6];
    const float* Wnin   = (const float*)d_in[7];
    const int*   nbr    = (const int*)d_in[8];
    const void*  mask   = d_in[9];
    float*       out    = (float*)d_out;

    const int N = in_sizes[0] / AA;

    float *p_out1, *p_s1, *p_b1, *p_s2, *p_b2;
    cudaGetSymbolAddress((void**)&p_out1, g_out1);
    cudaGetSymbolAddress((void**)&p_s1,   g_s1);
    cudaGetSymbolAddress((void**)&p_b1,   g_b1);
    cudaGetSymbolAddress((void**)&p_s2,   g_s2);
    cudaGetSymbolAddress((void**)&p_b2,   g_b2);

    const int gtiles = (N + 127) / 128;
    const int wtot   = KK * 2 * 128 * 16 + KK * 4 * 128 * 16 + 2 * 128 * 16;

    // mask dtype detect, gather-index precompute, weight pack
    k_detect<<<1, 256>>>((const unsigned char*)mask);
    k_gidx<<<(N + 255) / 256, 256>>>(nbr, mask, N);
    k_wcvt<<<(wtot + 255) / 256, 256>>>(W1, W2, Wnin);

    // BN1 folded affine
    k_stats<AA, 4><<<PB, dim3(AA, 4)>>>(feat, N);
    k_fin<AA><<<1, AA>>>(gamma1, beta1, p_s1, p_b1, N);

    // conv1 (fused, output-stationary) -> g_out1
    k_conv<AA, 1><<<gtiles, 256>>>(feat, p_out1, N);

    // BN2 folded affine
    k_stats<BB, 2><<<PB, dim3(BB, 2)>>>(p_out1, N);
    k_fin<BB><<<1, BB>>>(gamma2, beta2, p_s2, p_b2, N);

    // NiN shortcut (dense, initializes out), then conv2 RMW-adds
    k_conv<AA, 0><<<gtiles, 256>>>(feat, out, N);
    k_conv<BB, 2><<<gtiles, 256>>>(p_out1, out, N);
}

// round 8
// speedup vs baseline: 2.2317x; 1.0212x over previous
#include <cuda_runtime.h>
#include <cuda_bf16.h>
#include <cstdint>

// ---------------------------------------------------------------------------
// ResidualBlock: y = feat@Wnin + subconv(bnrelu2(subconv(bnrelu1(feat),W1)),W2)
// N=100000, A=64, B=128, K=27. fp32 in/out.
// Engine: mma.sync m16n8k16 bf16 (HMMA), 3-term hi/lo split, fp32 accum.
// Structure: fused output-stationary conv kernels, linear weight walk,
// register-staged 1-ahead pipeline (LDG(s+1) issued under MMA(s) shadow).
// Mask semantics: masked-off rows contribute TRUE zeros (affine only on valid
// gathered rows) — reference masks POST-bnrelu features.
// ---------------------------------------------------------------------------

#define KK   27
#define AA   64
#define BB   128
#define NMAX 100000
#define PB   512

// ---------------- static device scratch ------------------------------------
__device__ float g_out1[(size_t)NMAX * BB];                 // conv1 out (fp32)
__device__ int   g_gidx[KK * NMAX];                         // gather idx or -1
__device__ int   g_mask_u8;
__device__ float g_ps[PB * BB], g_pq[PB * BB];
__device__ float g_s1[AA], g_b1[AA], g_s2[BB], g_b2[BB];
// packed weights per (k, chunk): [hi plane 2560 u32][lo plane 2560 u32]
// plane layout: n*20 + slot(p), p = k-pair index 0..15. Stage-linear order.
__device__ __align__(16) uint32_t g_W1p[KK * 2 * 2 * 2560];
__device__ __align__(16) uint32_t g_W2p[KK * 4 * 2 * 2560];
__device__ __align__(16) uint32_t g_Wnp[2 * 2 * 2560];

// pair p (0..15) -> interleaved slot so fragment reg pairs are adjacent
__host__ __device__ __forceinline__ int pslot(int p) {
    return (p >> 3) * 8 + ((p & 3) * 2) + ((p & 7) >> 2);
}

// pack two fp32 -> bf16x2 (low half = first arg)
__device__ __forceinline__ uint32_t cvt2(float lo, float hi) {
    uint32_t r;
    asm("cvt.rn.bf16x2.f32 %0, %1, %2;" : "=r"(r) : "f"(hi), "f"(lo));
    return r;
}

// mma.sync m16n8k16 bf16: a={aL.x,aH.x,aL.y,aH.y}, b={b.x,b.y}, d += a@b
__device__ __forceinline__ void mma_bf(float* d, uint2 aL, uint2 aH, uint2 b) {
    asm volatile(
        "mma.sync.aligned.m16n8k16.row.col.f32.bf16.bf16.f32 "
        "{%0,%1,%2,%3}, {%4,%5,%6,%7}, {%8,%9}, {%0,%1,%2,%3};"
        : "+f"(d[0]), "+f"(d[1]), "+f"(d[2]), "+f"(d[3])
        : "r"(aL.x), "r"(aH.x), "r"(aL.y), "r"(aH.y), "r"(b.x), "r"(b.y));
}

// ---------------- small kernels --------------------------------------------
__global__ void k_detect(const unsigned char* __restrict__ m8) {
    int t = threadIdx.x;
    int ok = (m8[t * KK + KK / 2] != 0) ? 1 : 0;
    int all = __syncthreads_and(ok);
    if (t == 0) g_mask_u8 = all;
}

// precompute gather index per (k, site): masked neighbor or -1
__global__ void k_gidx(const int* __restrict__ nbr,
                       const void* __restrict__ mp, int N) {
    int i = blockIdx.x * blockDim.x + threadIdx.x;
    if (i >= N) return;
    const bool u8 = (g_mask_u8 != 0);
    const unsigned char* m8  = (const unsigned char*)mp;
    const int*           m32 = (const int*)mp;
#pragma unroll
    for (int k = 0; k < KK; k++) {
        bool m = u8 ? (m8[(size_t)i * KK + k] != 0)
                    : (m32[(size_t)i * KK + k] != 0);
        g_gidx[k * N + i] = m ? nbr[(size_t)i * KK + k] : -1;
    }
}

template <int CH, int RG>
__global__ void k_stats(const float* __restrict__ x, int N) {
    int c = threadIdx.x, r = threadIdx.y;
    float s = 0.f, q = 0.f;
    for (int i = blockIdx.x * RG + r; i < N; i += gridDim.x * RG) {
        float v = x[(size_t)i * CH + c];
        s += v; q += v * v;
    }
    __shared__ float sh[RG][CH];
    __shared__ float shq[RG][CH];
    sh[r][c] = s; shq[r][c] = q;
    __syncthreads();
    if (r == 0) {
#pragma unroll
        for (int j = 1; j < RG; j++) { s += sh[j][c]; q += shq[j][c]; }
        g_ps[blockIdx.x * CH + c] = s;
        g_pq[blockIdx.x * CH + c] = q;
    }
}

// parallel partial-reduce finisher: block (CH, 8)
template <int CH>
__global__ void k_fin(const float* __restrict__ gamma,
                      const float* __restrict__ beta,
                      float* __restrict__ scl, float* __restrict__ bia, int N) {
    int c = threadIdx.x, r = threadIdx.y;
    float s = 0.f, q = 0.f;
    for (int b = r; b < PB; b += 8) { s += g_ps[b * CH + c]; q += g_pq[b * CH + c]; }
    __shared__ float sh[8][CH];
    __shared__ float shq[8][CH];
    sh[r][c] = s; shq[r][c] = q;
    __syncthreads();
    if (r == 0) {
#pragma unroll
        for (int j = 1; j < 8; j++) { s += sh[j][c]; q += shq[j][c]; }
        float mu  = s / (float)N;
        float var = q / (float)N - mu * mu;
        if (var < 0.f) var = 0.f;
        float rs = rsqrtf(var + 1e-4f);
        float sc = gamma[c] * rs;
        scl[c] = sc;
        bia[c] = beta[c] - mu * sc;
    }
}

// weight pack: transpose-to-[n][k], bf16 hi/lo split, fragment-slot layout
__global__ void k_wcvt(const float* __restrict__ W1, const float* __restrict__ W2,
                       const float* __restrict__ Wn) {
    const int T1 = KK * 2 * 128 * 16;
    const int T2 = T1 + KK * 4 * 128 * 16;
    const int T3 = T2 + 2 * 128 * 16;
    int idx = blockIdx.x * blockDim.x + threadIdx.x;
    if (idx >= T3) return;
    const float* src; uint32_t* dst; int n, p;
    if (idx < T1) {
        int k = idx / (2 * 128 * 16), r = idx % (2 * 128 * 16);
        int ch = r / (128 * 16), r2 = r % (128 * 16);
        n = r2 / 16; p = r2 % 16;
        src = W1 + (size_t)k * 64 * 128 + (size_t)(ch * 32 + 2 * p) * 128 + n;
        dst = g_W1p + ((size_t)(k * 2 + ch) * 2) * 2560;
    } else if (idx < T2) {
        int i2 = idx - T1;
        int k = i2 / (4 * 128 * 16), r = i2 % (4 * 128 * 16);
        int ch = r / (128 * 16), r2 = r % (128 * 16);
        n = r2 / 16; p = r2 % 16;
        src = W2 + (size_t)k * 128 * 128 + (size_t)(ch * 32 + 2 * p) * 128 + n;
        dst = g_W2p + ((size_t)(k * 4 + ch) * 2) * 2560;
    } else {
        int i2 = idx - T2;
        int ch = i2 / (128 * 16), r2 = i2 % (128 * 16);
        n = r2 / 16; p = r2 % 16;
        src = Wn + (size_t)(ch * 32 + 2 * p) * 128 + n;
        dst = g_Wnp + ((size_t)ch * 2) * 2560;
    }
    float w0 = src[0], w1 = src[128];
    __nv_bfloat16 h0 = __float2bfloat16(w0);
    __nv_bfloat16 h1 = __float2bfloat16(w1);
    float l0 = w0 - __bfloat162float(h0);
    float l1 = w1 - __bfloat162float(h1);
    uint32_t hp = ((uint32_t)*(unsigned short*)&h1 << 16) |
                  (uint32_t)*(unsigned short*)&h0;
    int off = n * 20 + pslot(p);
    dst[off] = hp;
    __nv_bfloat16 e0 = __float2bfloat16(l0);
    __nv_bfloat16 e1 = __float2bfloat16(l1);
    uint32_t lp = ((uint32_t)*(unsigned short*)&e1 << 16) |
                  (uint32_t)*(unsigned short*)&e0;
    dst[2560 + off] = lp;
}

// ---------------- fused output-stationary conv kernel ------------------------
// MODE 0: out  = feat @ Wnin          (2 stages, dense, no affine, store)
// MODE 1: out1 = sum_k bnrelu1(feat)[gidx] @ W1[k]   (54 stages, store)
// MODE 2: out += sum_k bnrelu2(out1)[gidx] @ W2[k]   (108 stages, RMW add)
// Block: 128 sites x 128 cols, D in fp32 regs; 8 warps (4M x 2N).
// Stage s: k = s/NCH, chunk = s%NCH; weights consumed LINEARLY (bp = s*5120).
// Pipeline: A/B for stage s+1 loaded into REGISTERS right after STS(s); their
// LDG latency hides under MMA(s) + barrier. Masked rows are true zeros.

template <int CIN, int MODE>
__global__ void __launch_bounds__(256, 2) k_conv(
    const float* __restrict__ src, float* __restrict__ outp, int N) {

    constexpr int NCH = CIN / 32;
    constexpr int NK  = (MODE == 0) ? 1 : KK;
    constexpr int S   = NK * NCH;

    __shared__ __align__(16) uint32_t Ah[128 * 20];
    __shared__ __align__(16) uint32_t Al[128 * 20];
    __shared__ __align__(16) uint32_t Bs[2 * 2560];
    __shared__ float s_s[CIN], s_b[CIN];

    const uint32_t* Wb = (MODE == 0) ? g_Wnp : (MODE == 1 ? g_W1p : g_W2p);

    const int tid = threadIdx.x;
    const int wid = tid >> 5, lane = tid & 31;
    const int qr = lane >> 2, qc = lane & 3;
    const int wm = wid >> 1, wn = wid & 1;
    const int tile = blockIdx.x * 128;
    const int r = tid >> 1, h = tid & 1;
    const int site = tile + r;

    if (MODE != 0) {
        for (int c = tid; c < CIN; c += 256) {
            s_s[c] = (MODE == 1) ? g_s1[c] : g_s2[c];
            s_b[c] = (MODE == 1) ? g_b1[c] : g_b2[c];
        }
    }

    float acc[2][8][4];
#pragma unroll
    for (int a = 0; a < 2; a++)
#pragma unroll
        for (int b = 0; b < 8; b++)
#pragma unroll
            for (int c = 0; c < 4; c++) acc[a][b][c] = 0.f;

    // ---- staged registers for stage s (loaded 1 stage ahead)
    float4 rA[4];
    uint4  rB[5];
    int    srC;          // gather row of staged stage (-1 = masked/oob)
    int    c0C;          // channel base of staged stage

    // load stage-`s` A/B into registers
    auto ldStage = [&](int s) {
        const int k  = s / NCH;
        c0C = (s % NCH) * 32;
        if (MODE == 0) srC = (site < N) ? site : -1;
        else           srC = (site < N) ? g_gidx[(size_t)k * N + site] : -1;
        const float4* rp =
            (const float4*)(src + (size_t)srC * CIN + c0C + h * 16);
#pragma unroll
        for (int j = 0; j < 4; j++) {
            rA[j] = make_float4(0.f, 0.f, 0.f, 0.f);
            if (srC >= 0) rA[j] = rp[j];
        }
        const uint4* wp =
            (const uint4*)((const char*)(Wb + (size_t)s * 5120) + (size_t)tid * 16);
#pragma unroll
        for (int j = 0; j < 5; j++) rB[j] = wp[(size_t)j * 256];
    };

    // ---- prologue
    ldStage(0);

    for (int s = 0; s < S; s++) {
        const int sr = srC;
        const int c0 = c0C;
        float4 vA[4];
#pragma unroll
        for (int j = 0; j < 4; j++) vA[j] = rA[j];
        uint4 vB[5];
#pragma unroll
        for (int j = 0; j < 5; j++) vB[j] = rB[j];

        __syncthreads();               // MMA(s-1) done; s=0: s_s/s_b ready

        // ---- B store: linear copy of packed hi+lo planes
        {
            char* bp = (char*)Bs + (size_t)tid * 16;
#pragma unroll
            for (int j = 0; j < 5; j++) *(uint4*)(bp + (size_t)j * 4096) = vB[j];
        }
        // ---- A store: affine/relu ONLY on valid rows + hi/lo split
        {
            const uint32_t abase = (uint32_t)r * 20u + (uint32_t)h * 8u;
            const int cb = c0 + h * 16;
#pragma unroll
            for (int j = 0; j < 4; j++) {
                float4 v = vA[j];
                if (MODE != 0 && sr >= 0) {
                    int c = cb + j * 4;
                    v.x = fmaxf(fmaf(v.x, s_s[c],     s_b[c]),     0.f);
                    v.y = fmaxf(fmaf(v.y, s_s[c + 1], s_b[c + 1]), 0.f);
                    v.z = fmaxf(fmaf(v.z, s_s[c + 2], s_b[c + 2]), 0.f);
                    v.w = fmaxf(fmaf(v.w, s_s[c + 3], s_b[c + 3]), 0.f);
                }
                uint32_t p0 = cvt2(v.x, v.y);
                uint32_t p1 = cvt2(v.z, v.w);
                float rx = v.x - __uint_as_float(p0 << 16);
                float ry = v.y - __uint_as_float(p0 & 0xffff0000u);
                float rz = v.z - __uint_as_float(p1 << 16);
                float rw = v.w - __uint_as_float(p1 & 0xffff0000u);
                uint32_t q0 = cvt2(rx, ry);
                uint32_t q1 = cvt2(rz, rw);
                const int s0 = pslot(h * 8 + j * 2) - h * 8;
                const int s1 = pslot(h * 8 + j * 2 + 1) - h * 8;
                Ah[abase + s0] = p0;  Ah[abase + s1] = p1;
                Al[abase + s0] = q0;  Al[abase + s1] = q1;
            }
        }

        // ---- issue next stage's LDGs (latency hides under MMA below)
        if (s + 1 < S) ldStage(s + 1);

        __syncthreads();               // fills visible

        // ---- MMA: 2 k16 steps x 3 split terms x (2 M x 8 N tiles)
#pragma unroll
        for (int g = 0; g < 2; g++) {
            uint2 ah[2][2], al[2][2], bf[8];
#pragma unroll
            for (int mt = 0; mt < 2; mt++) {
                int r0 = wm * 32 + mt * 16 + qr;
                int o0 = r0 * 20 + g * 8 + qc * 2;
                int o1 = (r0 + 8) * 20 + g * 8 + qc * 2;
                ah[mt][0] = *(const uint2*)&Ah[o0];
                ah[mt][1] = *(const uint2*)&Ah[o1];
                al[mt][0] = *(const uint2*)&Al[o0];
                al[mt][1] = *(const uint2*)&Al[o1];
            }
#pragma unroll
            for (int nt = 0; nt < 8; nt++) {
                int c0b = wn * 64 + nt * 8 + qr;
                bf[nt] = *(const uint2*)&Bs[c0b * 20 + g * 8 + qc * 2];
            }
#pragma unroll
            for (int mt = 0; mt < 2; mt++)
#pragma unroll
                for (int nt = 0; nt < 8; nt++)
                    mma_bf(acc[mt][nt], ah[mt][0], ah[mt][1], bf[nt]);  // hi*hi
#pragma unroll
            for (int mt = 0; mt < 2; mt++)
#pragma unroll
                for (int nt = 0; nt < 8; nt++)
                    mma_bf(acc[mt][nt], al[mt][0], al[mt][1], bf[nt]);  // lo*hi
#pragma unroll
            for (int nt = 0; nt < 8; nt++) {
                int c0b = wn * 64 + nt * 8 + qr;
                bf[nt] = *(const uint2*)&Bs[2560 + c0b * 20 + g * 8 + qc * 2];
            }
#pragma unroll
            for (int mt = 0; mt < 2; mt++)
#pragma unroll
                for (int nt = 0; nt < 8; nt++)
                    mma_bf(acc[mt][nt], ah[mt][0], ah[mt][1], bf[nt]);  // hi*lo
        }
    }

    // ---- epilogue: store (MODE 0/1) or RMW add (MODE 2)
#pragma unroll
    for (int mt = 0; mt < 2; mt++) {
        int r0 = wm * 32 + mt * 16 + qr;
        int sA = tile + r0, sB = tile + r0 + 8;
#pragma unroll
        for (int nt = 0; nt < 8; nt++) {
            int col = wn * 64 + nt * 8 + qc * 2;
            if (sA < N) {
                float2* p = (float2*)(outp + (size_t)sA * BB + col);
                if (MODE == 2) {
                    float2 v = *p;
                    v.x += acc[mt][nt][0]; v.y += acc[mt][nt][1];
                    *p = v;
                } else {
                    *p = make_float2(acc[mt][nt][0], acc[mt][nt][1]);
                }
            }
            if (sB < N) {
                float2* p = (float2*)(outp + (size_t)sB * BB + col);
                if (MODE == 2) {
                    float2 v = *p;
                    v.x += acc[mt][nt][2]; v.y += acc[mt][nt][3];
                    *p = v;
                } else {
                    *p = make_float2(acc[mt][nt][2], acc[mt][nt][3]);
                }
            }
        }
    }
}

// ---------------------------------------------------------------------------
extern "C" void kernel_launch(void* const* d_in, const int* in_sizes, int n_in,
                              void* d_out, int out_size) {
    const float* feat   = (const float*)d_in[0];
    const float* gamma1 = (const float*)d_in[1];
    const float* beta1  = (const float*)d_in[2];
    const float* W1     = (const float*)d_in[3];
    const float* gamma2 = (const float*)d_in[4];
    const float* beta2  = (const float*)d_in[5];
    const float* W2     = (const float*)d_in[6];
    const float* Wnin   = (const float*)d_in[7];
    const int*   nbr    = (const int*)d_in[8];
    const void*  mask   = d_in[9];
    float*       out    = (float*)d_out;

    const int N = in_sizes[0] / AA;

    float *p_out1, *p_s1, *p_b1, *p_s2, *p_b2;
    cudaGetSymbolAddress((void**)&p_out1, g_out1);
    cudaGetSymbolAddress((void**)&p_s1,   g_s1);
    cudaGetSymbolAddress((void**)&p_b1,   g_b1);
    cudaGetSymbolAddress((void**)&p_s2,   g_s2);
    cudaGetSymbolAddress((void**)&p_b2,   g_b2);

    const int gtiles = (N + 127) / 128;
    const int wtot   = KK * 2 * 128 * 16 + KK * 4 * 128 * 16 + 2 * 128 * 16;

    // mask dtype detect, gather-index precompute, weight pack
    k_detect<<<1, 256>>>((const unsigned char*)mask);
    k_gidx<<<(N + 255) / 256, 256>>>(nbr, mask, N);
    k_wcvt<<<(wtot + 255) / 256, 256>>>(W1, W2, Wnin);

    // BN1 folded affine
    k_stats<AA, 4><<<PB, dim3(AA, 4)>>>(feat, N);
    k_fin<AA><<<1, dim3(AA, 8)>>>(gamma1, beta1, p_s1, p_b1, N);

    // conv1 (fused, output-stationary, pipelined) -> g_out1
    k_conv<AA, 1><<<gtiles, 256>>>(feat, p_out1, N);

    // BN2 folded affine
    k_stats<BB, 2><<<PB, dim3(BB, 2)>>>(p_out1, N);
    k_fin<BB><<<1, dim3(BB, 8)>>>(gamma2, beta2, p_s2, p_b2, N);

    // NiN shortcut (dense, initializes out), then conv2 RMW-adds
    k_conv<AA, 0><<<gtiles, 256>>>(feat, out, N);
    k_conv<BB, 2><<<gtiles, 256>>>(p_out1, out, N);
}

// round 9
// speedup vs baseline: 4.0640x; 1.8211x over previous
#include <cuda_runtime.h>
#include <cuda_fp16.h>
#include <cstdint>

// ---------------------------------------------------------------------------
// ResidualBlock: y = feat@Wnin + subconv(bnrelu2(subconv(bnrelu1(feat),W1)),W2)
// N=100000, A=64, B=128, K=27. fp32 in/out.
// Engine: mma.sync m16n8k16 fp16 (HMMA), SINGLE PASS, fp32 accum.
//   (error ~2^-11 per product, fp32 accumulate -> rel_err ~3e-4 < 1e-3)
// Structure: fused output-stationary conv kernels, linear weight walk,
// register-staged 1-ahead pipeline, no reg copies (fits 128-reg/2-CTA).
// Mask semantics: masked-off rows contribute TRUE zeros.
// ---------------------------------------------------------------------------

#define KK   27
#define AA   64
#define BB   128
#define NMAX 100000
#define PB   512

// ---------------- static device scratch ------------------------------------
__device__ float g_out1[(size_t)NMAX * BB];                 // conv1 out (fp32)
__device__ int   g_gidx[KK * NMAX];                         // gather idx or -1
__device__ int   g_mask_u8;
__device__ float g_ps[PB * BB], g_pq[PB * BB];
__device__ float g_s1[AA], g_b1[AA], g_s2[BB], g_b2[BB];
// packed fp16 weights per (k, chunk): 2560 u32, layout n*20 + slot(p)
__device__ __align__(16) uint32_t g_W1p[KK * 2 * 2560];
__device__ __align__(16) uint32_t g_W2p[KK * 4 * 2560];
__device__ __align__(16) uint32_t g_Wnp[2 * 2560];

// pair p (0..15) -> interleaved slot so fragment reg pairs are adjacent
__host__ __device__ __forceinline__ int pslot(int p) {
    return (p >> 3) * 8 + ((p & 3) * 2) + ((p & 7) >> 2);
}

// pack two fp32 -> f16x2 (low half = first arg)
__device__ __forceinline__ uint32_t cvt2(float lo, float hi) {
    uint32_t r;
    asm("cvt.rn.f16x2.f32 %0, %1, %2;" : "=r"(r) : "f"(hi), "f"(lo));
    return r;
}

// mma.sync m16n8k16 f16: a={a0.x,a1.x,a0.y,a1.y}, b={b.x,b.y}, d += a@b
__device__ __forceinline__ void mma_f16(float* d, uint2 a0, uint2 a1, uint2 b) {
    asm volatile(
        "mma.sync.aligned.m16n8k16.row.col.f32.f16.f16.f32 "
        "{%0,%1,%2,%3}, {%4,%5,%6,%7}, {%8,%9}, {%0,%1,%2,%3};"
        : "+f"(d[0]), "+f"(d[1]), "+f"(d[2]), "+f"(d[3])
        : "r"(a0.x), "r"(a1.x), "r"(a0.y), "r"(a1.y), "r"(b.x), "r"(b.y));
}

// ---------------- small kernels --------------------------------------------
__global__ void k_detect(const unsigned char* __restrict__ m8) {
    int t = threadIdx.x;
    int ok = (m8[t * KK + KK / 2] != 0) ? 1 : 0;
    int all = __syncthreads_and(ok);
    if (t == 0) g_mask_u8 = all;
}

// precompute gather index per (k, site): masked neighbor or -1
__global__ void k_gidx(const int* __restrict__ nbr,
                       const void* __restrict__ mp, int N) {
    int i = blockIdx.x * blockDim.x + threadIdx.x;
    if (i >= N) return;
    const bool u8 = (g_mask_u8 != 0);
    const unsigned char* m8  = (const unsigned char*)mp;
    const int*           m32 = (const int*)mp;
#pragma unroll
    for (int k = 0; k < KK; k++) {
        bool m = u8 ? (m8[(size_t)i * KK + k] != 0)
                    : (m32[(size_t)i * KK + k] != 0);
        g_gidx[k * N + i] = m ? nbr[(size_t)i * KK + k] : -1;
    }
}

template <int CH, int RG>
__global__ void k_stats(const float* __restrict__ x, int N) {
    int c = threadIdx.x, r = threadIdx.y;
    float s = 0.f, q = 0.f;
    for (int i = blockIdx.x * RG + r; i < N; i += gridDim.x * RG) {
        float v = x[(size_t)i * CH + c];
        s += v; q += v * v;
    }
    __shared__ float sh[RG][CH];
    __shared__ float shq[RG][CH];
    sh[r][c] = s; shq[r][c] = q;
    __syncthreads();
    if (r == 0) {
#pragma unroll
        for (int j = 1; j < RG; j++) { s += sh[j][c]; q += shq[j][c]; }
        g_ps[blockIdx.x * CH + c] = s;
        g_pq[blockIdx.x * CH + c] = q;
    }
}

// parallel partial-reduce finisher: block (CH, 8)
template <int CH>
__global__ void k_fin(const float* __restrict__ gamma,
                      const float* __restrict__ beta,
                      float* __restrict__ scl, float* __restrict__ bia, int N) {
    int c = threadIdx.x, r = threadIdx.y;
    float s = 0.f, q = 0.f;
    for (int b = r; b < PB; b += 8) { s += g_ps[b * CH + c]; q += g_pq[b * CH + c]; }
    __shared__ float sh[8][CH];
    __shared__ float shq[8][CH];
    sh[r][c] = s; shq[r][c] = q;
    __syncthreads();
    if (r == 0) {
#pragma unroll
        for (int j = 1; j < 8; j++) { s += sh[j][c]; q += shq[j][c]; }
        float mu  = s / (float)N;
        float var = q / (float)N - mu * mu;
        if (var < 0.f) var = 0.f;
        float rs = rsqrtf(var + 1e-4f);
        float sc = gamma[c] * rs;
        scl[c] = sc;
        bia[c] = beta[c] - mu * sc;
    }
}

// weight pack: transpose-to-[n][k], fp16, fragment-slot layout, stage-linear
__global__ void k_wcvt(const float* __restrict__ W1, const float* __restrict__ W2,
                       const float* __restrict__ Wn) {
    const int T1 = KK * 2 * 128 * 16;
    const int T2 = T1 + KK * 4 * 128 * 16;
    const int T3 = T2 + 2 * 128 * 16;
    int idx = blockIdx.x * blockDim.x + threadIdx.x;
    if (idx >= T3) return;
    const float* src; uint32_t* dst; int n, p;
    if (idx < T1) {
        int k = idx / (2 * 128 * 16), r = idx % (2 * 128 * 16);
        int ch = r / (128 * 16), r2 = r % (128 * 16);
        n = r2 / 16; p = r2 % 16;
        src = W1 + (size_t)k * 64 * 128 + (size_t)(ch * 32 + 2 * p) * 128 + n;
        dst = g_W1p + (size_t)(k * 2 + ch) * 2560;
    } else if (idx < T2) {
        int i2 = idx - T1;
        int k = i2 / (4 * 128 * 16), r = i2 % (4 * 128 * 16);
        int ch = r / (128 * 16), r2 = r % (128 * 16);
        n = r2 / 16; p = r2 % 16;
        src = W2 + (size_t)k * 128 * 128 + (size_t)(ch * 32 + 2 * p) * 128 + n;
        dst = g_W2p + (size_t)(k * 4 + ch) * 2560;
    } else {
        int i2 = idx - T2;
        int ch = i2 / (128 * 16), r2 = i2 % (128 * 16);
        n = r2 / 16; p = r2 % 16;
        src = Wn + (size_t)(ch * 32 + 2 * p) * 128 + n;
        dst = g_Wnp + (size_t)ch * 2560;
    }
    float w0 = src[0], w1 = src[128];
    __half h0 = __float2half(w0);
    __half h1 = __float2half(w1);
    uint32_t hp = ((uint32_t)*(unsigned short*)&h1 << 16) |
                  (uint32_t)*(unsigned short*)&h0;
    dst[n * 20 + pslot(p)] = hp;
}

// ---------------- fused output-stationary conv kernel ------------------------
// MODE 0: out  = feat @ Wnin          (2 stages, dense, no affine, store)
// MODE 1: out1 = sum_k bnrelu1(feat)[gidx] @ W1[k]   (54 stages, store)
// MODE 2: out += sum_k bnrelu2(out1)[gidx] @ W2[k]   (108 stages, RMW add)
// Block: 128 sites x 128 cols, D in fp32 regs; 8 warps (4M x 2N).
// Stage s: weights consumed LINEARLY (bp = s*2560 u32). Register-staged
// 1-ahead: STS(s) from staged regs, then LDG(s+1) overwrites them (WAR ok).

template <int CIN, int MODE>
__global__ void __launch_bounds__(256, 2) k_conv(
    const float* __restrict__ src, float* __restrict__ outp, int N) {

    constexpr int NCH = CIN / 32;
    constexpr int NK  = (MODE == 0) ? 1 : KK;
    constexpr int S   = NK * NCH;

    __shared__ __align__(16) uint32_t Ah[128 * 20];
    __shared__ __align__(16) uint32_t Bs[2560];
    __shared__ float s_s[CIN], s_b[CIN];

    const uint32_t* Wb = (MODE == 0) ? g_Wnp : (MODE == 1 ? g_W1p : g_W2p);

    const int tid = threadIdx.x;
    const int wid = tid >> 5, lane = tid & 31;
    const int qr = lane >> 2, qc = lane & 3;
    const int wm = wid >> 1, wn = wid & 1;
    const int tile = blockIdx.x * 128;
    const int r = tid >> 1, h = tid & 1;
    const int site = tile + r;

    if (MODE != 0) {
        for (int c = tid; c < CIN; c += 256) {
            s_s[c] = (MODE == 1) ? g_s1[c] : g_s2[c];
            s_b[c] = (MODE == 1) ? g_b1[c] : g_b2[c];
        }
    }

    float acc[2][8][4];
#pragma unroll
    for (int a = 0; a < 2; a++)
#pragma unroll
        for (int b = 0; b < 8; b++)
#pragma unroll
            for (int c = 0; c < 4; c++) acc[a][b][c] = 0.f;

    // ---- staged registers (loaded 1 stage ahead, consumed by STS)
    float4 rA[4];
    uint4  rB[3];       // 2560 u32 = 640 uint4; threads cover 640 of 768 slots
    int    srC, c0C;

    auto ldStage = [&](int s) {
        const int k = s / NCH;
        c0C = (s % NCH) * 32;
        if (MODE == 0) srC = (site < N) ? site : -1;
        else           srC = (site < N) ? g_gidx[(size_t)k * N + site] : -1;
        const float4* rp =
            (const float4*)(src + (size_t)srC * CIN + c0C + h * 16);
#pragma unroll
        for (int j = 0; j < 4; j++) {
            rA[j] = make_float4(0.f, 0.f, 0.f, 0.f);
            if (srC >= 0) rA[j] = rp[j];
        }
        const uint4* wp = (const uint4*)(Wb + (size_t)s * 2560);
#pragma unroll
        for (int j = 0; j < 3; j++) {
            int idx = tid + j * 256;
            if (idx < 640) rB[j] = wp[idx];
        }
    };

    // ---- prologue
    ldStage(0);

    for (int s = 0; s < S; s++) {
        __syncthreads();               // MMA(s-1) done; s=0: s_s/s_b ready

        // ---- B store: linear copy of packed fp16 plane (2560 u32)
        {
            uint4* bd = (uint4*)Bs;
#pragma unroll
            for (int j = 0; j < 3; j++) {
                int idx = tid + j * 256;
                if (idx < 640) bd[idx] = rB[j];
            }
        }
        // ---- A store: affine/relu ONLY on valid rows, fp16 convert
        {
            const int sr = srC;
            const uint32_t abase = (uint32_t)r * 20u + (uint32_t)h * 8u;
            const int cb = c0C + h * 16;
#pragma unroll
            for (int j = 0; j < 4; j++) {
                float4 v = rA[j];
                if (MODE != 0 && sr >= 0) {
                    int c = cb + j * 4;
                    v.x = fmaxf(fmaf(v.x, s_s[c],     s_b[c]),     0.f);
                    v.y = fmaxf(fmaf(v.y, s_s[c + 1], s_b[c + 1]), 0.f);
                    v.z = fmaxf(fmaf(v.z, s_s[c + 2], s_b[c + 2]), 0.f);
                    v.w = fmaxf(fmaf(v.w, s_s[c + 3], s_b[c + 3]), 0.f);
                }
                uint32_t p0 = cvt2(v.x, v.y);
                uint32_t p1 = cvt2(v.z, v.w);
                const int s0 = pslot(h * 8 + j * 2) - h * 8;
                const int s1 = pslot(h * 8 + j * 2 + 1) - h * 8;
                Ah[abase + s0] = p0;  Ah[abase + s1] = p1;
            }
        }

        // ---- issue next stage's LDGs (latency hides under MMA below)
        if (s + 1 < S) ldStage(s + 1);

        __syncthreads();               // fills visible

        // ---- MMA: 2 k16 steps x (2 M x 8 N tiles), single fp16 pass
#pragma unroll
        for (int g = 0; g < 2; g++) {
            uint2 a0[2], a1[2], bf[8];
#pragma unroll
            for (int mt = 0; mt < 2; mt++) {
                int r0 = wm * 32 + mt * 16 + qr;
                a0[mt] = *(const uint2*)&Ah[r0 * 20 + g * 8 + qc * 2];
                a1[mt] = *(const uint2*)&Ah[(r0 + 8) * 20 + g * 8 + qc * 2];
            }
#pragma unroll
            for (int nt = 0; nt < 8; nt++) {
                int c0b = wn * 64 + nt * 8 + qr;
                bf[nt] = *(const uint2*)&Bs[c0b * 20 + g * 8 + qc * 2];
            }
#pragma unroll
            for (int mt = 0; mt < 2; mt++)
#pragma unroll
                for (int nt = 0; nt < 8; nt++)
                    mma_f16(acc[mt][nt], a0[mt], a1[mt], bf[nt]);
        }
    }

    // ---- epilogue: store (MODE 0/1) or RMW add (MODE 2)
#pragma unroll
    for (int mt = 0; mt < 2; mt++) {
        int r0 = wm * 32 + mt * 16 + qr;
        int sA = tile + r0, sB = tile + r0 + 8;
#pragma unroll
        for (int nt = 0; nt < 8; nt++) {
            int col = wn * 64 + nt * 8 + qc * 2;
            if (sA < N) {
                float2* p = (float2*)(outp + (size_t)sA * BB + col);
                if (MODE == 2) {
                    float2 v = *p;
                    v.x += acc[mt][nt][0]; v.y += acc[mt][nt][1];
                    *p = v;
                } else {
                    *p = make_float2(acc[mt][nt][0], acc[mt][nt][1]);
                }
            }
            if (sB < N) {
                float2* p = (float2*)(outp + (size_t)sB * BB + col);
                if (MODE == 2) {
                    float2 v = *p;
                    v.x += acc[mt][nt][2]; v.y += acc[mt][nt][3];
                    *p = v;
                } else {
                    *p = make_float2(acc[mt][nt][2], acc[mt][nt][3]);
                }
            }
        }
    }
}

// ---------------------------------------------------------------------------
extern "C" void kernel_launch(void* const* d_in, const int* in_sizes, int n_in,
                              void* d_out, int out_size) {
    const float* feat   = (const float*)d_in[0];
    const float* gamma1 = (const float*)d_in[1];
    const float* beta1  = (const float*)d_in[2];
    const float* W1     = (const float*)d_in[3];
    const float* gamma2 = (const float*)d_in[4];
    const float* beta2  = (const float*)d_in[5];
    const float* W2     = (const float*)d_in[6];
    const float* Wnin   = (const float*)d_in[7];
    const int*   nbr    = (const int*)d_in[8];
    const void*  mask   = d_in[9];
    float*       out    = (float*)d_out;

    const int N = in_sizes[0] / AA;

    float *p_out1, *p_s1, *p_b1, *p_s2, *p_b2;
    cudaGetSymbolAddress((void**)&p_out1, g_out1);
    cudaGetSymbolAddress((void**)&p_s1,   g_s1);
    cudaGetSymbolAddress((void**)&p_b1,   g_b1);
    cudaGetSymbolAddress((void**)&p_s2,   g_s2);
    cudaGetSymbolAddress((void**)&p_b2,   g_b2);

    const int gtiles = (N + 127) / 128;
    const int wtot   = KK * 2 * 128 * 16 + KK * 4 * 128 * 16 + 2 * 128 * 16;

    // mask dtype detect, gather-index precompute, weight pack
    k_detect<<<1, 256>>>((const unsigned char*)mask);
    k_gidx<<<(N + 255) / 256, 256>>>(nbr, mask, N);
    k_wcvt<<<(wtot + 255) / 256, 256>>>(W1, W2, Wnin);

    // BN1 folded affine
    k_stats<AA, 4><<<PB, dim3(AA, 4)>>>(feat, N);
    k_fin<AA><<<1, dim3(AA, 8)>>>(gamma1, beta1, p_s1, p_b1, N);

    // conv1 (fused, output-stationary, pipelined) -> g_out1
    k_conv<AA, 1><<<gtiles, 256>>>(feat, p_out1, N);

    // BN2 folded affine
    k_stats<BB, 2><<<PB, dim3(BB, 2)>>>(p_out1, N);
    k_fin<BB><<<1, dim3(BB, 8)>>>(gamma2, beta2, p_s2, p_b2, N);

    // NiN shortcut (dense, initializes out), then conv2 RMW-adds
    k_conv<AA, 0><<<gtiles, 256>>>(feat, out, N);
    k_conv<BB, 2><<<gtiles, 256>>>(p_out1, out, N);
}

// round 10
// speedup vs baseline: 4.5378x; 1.1166x over previous
#include <cuda_runtime.h>
#include <cuda_fp16.h>
#include <cstdint>

// ---------------------------------------------------------------------------
// ResidualBlock: y = feat@Wnin + subconv(bnrelu2(subconv(bnrelu1(feat),W1)),W2)
// N=100000, A=64, B=128, K=27. fp32 in/out.
// Engine: mma.sync m16n8k16 fp16 (HMMA), single pass, fp32 accum.
// Round-10: fp16 gather sources (feat16/mid16), gidx prefetch 2 ahead,
// reduced fragment registers (no spills at 128-reg/2-CTA budget).
// Mask semantics: masked-off rows contribute TRUE zeros.
// ---------------------------------------------------------------------------

#define KK   27
#define AA   64
#define BB   128
#define NMAX 100000
#define PB   512

// ---------------- static device scratch ------------------------------------
__device__ float g_out1[(size_t)NMAX * BB];                  // conv1 out fp32
__device__ __align__(16) unsigned short g_mid16[(size_t)NMAX * BB];
__device__ __align__(16) unsigned short g_feat16[(size_t)NMAX * AA];
__device__ int   g_gidx[KK * NMAX];                          // gather idx / -1
__device__ int   g_mask_u8;
__device__ float g_ps[PB * BB], g_pq[PB * BB];
__device__ float g_s1[AA], g_b1[AA], g_s2[BB], g_b2[BB];
// packed fp16 weights per (k, chunk): 2560 u32, layout n*20 + slot(p)
__device__ __align__(16) uint32_t g_W1p[KK * 2 * 2560];
__device__ __align__(16) uint32_t g_W2p[KK * 4 * 2560];
__device__ __align__(16) uint32_t g_Wnp[2 * 2560];

// pair p (0..15) -> interleaved slot so fragment reg pairs are adjacent
__host__ __device__ __forceinline__ int pslot(int p) {
    return (p >> 3) * 8 + ((p & 3) * 2) + ((p & 7) >> 2);
}

// pack two fp32 -> f16x2 (low half = first arg)
__device__ __forceinline__ uint32_t cvt2(float lo, float hi) {
    uint32_t r;
    asm("cvt.rn.f16x2.f32 %0, %1, %2;" : "=r"(r) : "f"(hi), "f"(lo));
    return r;
}

// mma.sync m16n8k16 f16: a={a0.x,a1.x,a0.y,a1.y}, b={b.x,b.y}, d += a@b
__device__ __forceinline__ void mma_f16(float* d, uint2 a0, uint2 a1, uint2 b) {
    asm volatile(
        "mma.sync.aligned.m16n8k16.row.col.f32.f16.f16.f32 "
        "{%0,%1,%2,%3}, {%4,%5,%6,%7}, {%8,%9}, {%0,%1,%2,%3};"
        : "+f"(d[0]), "+f"(d[1]), "+f"(d[2]), "+f"(d[3])
        : "r"(a0.x), "r"(a1.x), "r"(a0.y), "r"(a1.y), "r"(b.x), "r"(b.y));
}

// ---------------- small kernels --------------------------------------------
__global__ void k_detect(const unsigned char* __restrict__ m8) {
    int t = threadIdx.x;
    int ok = (m8[t * KK + KK / 2] != 0) ? 1 : 0;
    int all = __syncthreads_and(ok);
    if (t == 0) g_mask_u8 = all;
}

// precompute gather index per (k, site)
__global__ void k_gidx(const int* __restrict__ nbr,
                       const void* __restrict__ mp, int N) {
    int i = blockIdx.x * blockDim.x + threadIdx.x;
    if (i >= N) return;
    const bool u8 = (g_mask_u8 != 0);
    const unsigned char* m8  = (const unsigned char*)mp;
    const int*           m32 = (const int*)mp;
#pragma unroll
    for (int k = 0; k < KK; k++) {
        bool m = u8 ? (m8[(size_t)i * KK + k] != 0)
                    : (m32[(size_t)i * KK + k] != 0);
        g_gidx[k * N + i] = m ? nbr[(size_t)i * KK + k] : -1;
    }
}

// feat fp32 -> fp16 (4 elems/thread)
__global__ void k_prep(const float* __restrict__ f, int n4) {
    int i = blockIdx.x * blockDim.x + threadIdx.x;
    if (i >= n4) return;
    float4 v = ((const float4*)f)[i];
    uint2 o;
    o.x = cvt2(v.x, v.y);
    o.y = cvt2(v.z, v.w);
    ((uint2*)g_feat16)[i] = o;
}

template <int CH, int RG>
__global__ void k_stats(const float* __restrict__ x, int N) {
    int c = threadIdx.x, r = threadIdx.y;
    float s = 0.f, q = 0.f;
    for (int i = blockIdx.x * RG + r; i < N; i += gridDim.x * RG) {
        float v = x[(size_t)i * CH + c];
        s += v; q += v * v;
    }
    __shared__ float sh[RG][CH];
    __shared__ float shq[RG][CH];
    sh[r][c] = s; shq[r][c] = q;
    __syncthreads();
    if (r == 0) {
#pragma unroll
        for (int j = 1; j < RG; j++) { s += sh[j][c]; q += shq[j][c]; }
        g_ps[blockIdx.x * CH + c] = s;
        g_pq[blockIdx.x * CH + c] = q;
    }
}

// parallel partial-reduce finisher: block (CH, 8)
template <int CH>
__global__ void k_fin(const float* __restrict__ gamma,
                      const float* __restrict__ beta,
                      float* __restrict__ scl, float* __restrict__ bia, int N) {
    int c = threadIdx.x, r = threadIdx.y;
    float s = 0.f, q = 0.f;
    for (int b = r; b < PB; b += 8) { s += g_ps[b * CH + c]; q += g_pq[b * CH + c]; }
    __shared__ float sh[8][CH];
    __shared__ float shq[8][CH];
    sh[r][c] = s; shq[r][c] = q;
    __syncthreads();
    if (r == 0) {
#pragma unroll
        for (int j = 1; j < 8; j++) { s += sh[j][c]; q += shq[j][c]; }
        float mu  = s / (float)N;
        float var = q / (float)N - mu * mu;
        if (var < 0.f) var = 0.f;
        float rs = rsqrtf(var + 1e-4f);
        float sc = gamma[c] * rs;
        scl[c] = sc;
        bia[c] = beta[c] - mu * sc;
    }
}

// weight pack: transpose-to-[n][k], fp16, fragment-slot layout, stage-linear
__global__ void k_wcvt(const float* __restrict__ W1, const float* __restrict__ W2,
                       const float* __restrict__ Wn) {
    const int T1 = KK * 2 * 128 * 16;
    const int T2 = T1 + KK * 4 * 128 * 16;
    const int T3 = T2 + 2 * 128 * 16;
    int idx = blockIdx.x * blockDim.x + threadIdx.x;
    if (idx >= T3) return;
    const float* src; uint32_t* dst; int n, p;
    if (idx < T1) {
        int k = idx / (2 * 128 * 16), r = idx % (2 * 128 * 16);
        int ch = r / (128 * 16), r2 = r % (128 * 16);
        n = r2 / 16; p = r2 % 16;
        src = W1 + (size_t)k * 64 * 128 + (size_t)(ch * 32 + 2 * p) * 128 + n;
        dst = g_W1p + (size_t)(k * 2 + ch) * 2560;
    } else if (idx < T2) {
        int i2 = idx - T1;
        int k = i2 / (4 * 128 * 16), r = i2 % (4 * 128 * 16);
        int ch = r / (128 * 16), r2 = r % (128 * 16);
        n = r2 / 16; p = r2 % 16;
        src = W2 + (size_t)k * 128 * 128 + (size_t)(ch * 32 + 2 * p) * 128 + n;
        dst = g_W2p + (size_t)(k * 4 + ch) * 2560;
    } else {
        int i2 = idx - T2;
        int ch = i2 / (128 * 16), r2 = i2 % (128 * 16);
        n = r2 / 16; p = r2 % 16;
        src = Wn + (size_t)(ch * 32 + 2 * p) * 128 + n;
        dst = g_Wnp + (size_t)ch * 2560;
    }
    float w0 = src[0], w1 = src[128];
    __half h0 = __float2half(w0);
    __half h1 = __float2half(w1);
    uint32_t hp = ((uint32_t)*(unsigned short*)&h1 << 16) |
                  (uint32_t)*(unsigned short*)&h0;
    dst[n * 20 + pslot(p)] = hp;
}

// ---------------- fused output-stationary conv kernel ------------------------
// MODE 0: out  = feat16 @ Wnin         (2 stages, dense, no affine, store)
// MODE 1: out1 = sum_k bnrelu1(feat16)[gidx] @ W1[k]  (54 st, store + mid16)
// MODE 2: out += sum_k bnrelu2(mid16)[gidx] @ W2[k]   (108 st, RMW add)
// Block: 128 sites x 128 cols, D in fp32 regs; 8 warps (4M x 2N).
// A sources are fp16 (1 uint4/thread/stage). gidx prefetched 2 stages ahead.

template <int CIN, int MODE>
__global__ void __launch_bounds__(256, 2) k_conv(
    const unsigned short* __restrict__ src16, float* __restrict__ outp, int N) {

    constexpr int NCH = CIN / 32;
    constexpr int NK  = (MODE == 0) ? 1 : KK;
    constexpr int S   = NK * NCH;

    __shared__ __align__(16) uint32_t Ah[128 * 20];
    __shared__ __align__(16) uint32_t Bs[2560];
    __shared__ float s_s[CIN], s_b[CIN];

    const uint32_t* Wb = (MODE == 0) ? g_Wnp : (MODE == 1 ? g_W1p : g_W2p);

    const int tid = threadIdx.x;
    const int wid = tid >> 5, lane = tid & 31;
    const int qr = lane >> 2, qc = lane & 3;
    const int wm = wid >> 1, wn = wid & 1;
    const int tile = blockIdx.x * 128;
    const int r = tid >> 1, h = tid & 1;
    const int site = tile + r;

    if (MODE != 0) {
        for (int c = tid; c < CIN; c += 256) {
            s_s[c] = (MODE == 1) ? g_s1[c] : g_s2[c];
            s_b[c] = (MODE == 1) ? g_b1[c] : g_b2[c];
        }
    }

    float acc[2][8][4];
#pragma unroll
    for (int a = 0; a < 2; a++)
#pragma unroll
        for (int b = 0; b < 8; b++)
#pragma unroll
            for (int c = 0; c < 4; c++) acc[a][b][c] = 0.f;

    // gather row for stage s (prefetch helper)
    auto rowOf = [&](int s) -> int {
        if (site >= N) return -1;
        if (MODE == 0) return site;
        return g_gidx[(size_t)(s / NCH) * N + site];
    };

    // staged data: rA2 = 16 fp16 channels; rB = weight plane chunk
    uint4 rA2[2];
    uint4 rB[3];
    int   srA;      // row of stage currently in rA2
    int   srN;      // prefetched row for the NEXT stage

    auto ldA = [&](int s, int sr) {
        const uint4* rp = (const uint4*)(src16 + (size_t)sr * CIN +
                                         (s % NCH) * 32 + h * 16);
        if (sr >= 0) { rA2[0] = rp[0]; rA2[1] = rp[1]; }
    };
    auto ldB = [&](int s) {
        const uint4* wp = (const uint4*)(Wb + (size_t)s * 2560);
#pragma unroll
        for (int j = 0; j < 3; j++) {
            int idx = tid + j * 256;
            if (idx < 640) rB[j] = wp[idx];
        }
    };

    // ---- prologue
    srA = rowOf(0);
    ldA(0, srA);
    ldB(0);
    srN = (S > 1) ? rowOf(1) : -1;

    for (int s = 0; s < S; s++) {
        __syncthreads();               // MMA(s-1) done; s=0: s_s/s_b ready

        // ---- B store (2560 u32 linear)
        {
            uint4* bd = (uint4*)Bs;
#pragma unroll
            for (int j = 0; j < 3; j++) {
                int idx = tid + j * 256;
                if (idx < 640) bd[idx] = rB[j];
            }
        }
        // ---- A store: unpack fp16, affine/relu on valid rows, repack
        {
            const int sr = srA;
            const uint32_t* aw = (const uint32_t*)rA2;
            const uint32_t abase = (uint32_t)r * 20u + (uint32_t)h * 8u;
            const int cb = (s % NCH) * 32 + h * 16;
#pragma unroll
            for (int j = 0; j < 4; j++) {
                uint32_t p0 = 0u, p1 = 0u;
                if (sr >= 0) {
                    uint32_t w0 = aw[2 * j], w1 = aw[2 * j + 1];
                    if (MODE != 0) {
                        float2 f0 = __half22float2(*(const __half2*)&w0);
                        float2 f1 = __half22float2(*(const __half2*)&w1);
                        int c = cb + j * 4;
                        f0.x = fmaxf(fmaf(f0.x, s_s[c],     s_b[c]),     0.f);
                        f0.y = fmaxf(fmaf(f0.y, s_s[c + 1], s_b[c + 1]), 0.f);
                        f1.x = fmaxf(fmaf(f1.x, s_s[c + 2], s_b[c + 2]), 0.f);
                        f1.y = fmaxf(fmaf(f1.y, s_s[c + 3], s_b[c + 3]), 0.f);
                        p0 = cvt2(f0.x, f0.y);
                        p1 = cvt2(f1.x, f1.y);
                    } else {
                        p0 = w0; p1 = w1;
                    }
                }
                const int s0 = pslot(h * 8 + j * 2) - h * 8;
                const int s1 = pslot(h * 8 + j * 2 + 1) - h * 8;
                Ah[abase + s0] = p0;  Ah[abase + s1] = p1;
            }
        }

        // ---- issue next stage's loads (addresses ready via prefetched srN)
        if (s + 1 < S) {
            ldA(s + 1, srN);
            ldB(s + 1);
        }
        srA = srN;
        if (s + 2 < S) srN = rowOf(s + 2);   // 2-ahead index prefetch

        __syncthreads();               // fills visible

        // ---- MMA: 2 k16 steps x (2 M x 8 N tiles); bf loaded per-nt
#pragma unroll
        for (int g = 0; g < 2; g++) {
            uint2 a0[2], a1[2];
#pragma unroll
            for (int mt = 0; mt < 2; mt++) {
                int r0 = wm * 32 + mt * 16 + qr;
                a0[mt] = *(const uint2*)&Ah[r0 * 20 + g * 8 + qc * 2];
                a1[mt] = *(const uint2*)&Ah[(r0 + 8) * 20 + g * 8 + qc * 2];
            }
#pragma unroll
            for (int nt = 0; nt < 8; nt++) {
                int c0b = wn * 64 + nt * 8 + qr;
                uint2 bf = *(const uint2*)&Bs[c0b * 20 + g * 8 + qc * 2];
                mma_f16(acc[0][nt], a0[0], a1[0], bf);
                mma_f16(acc[1][nt], a0[1], a1[1], bf);
            }
        }
    }

    // ---- epilogue
#pragma unroll
    for (int mt = 0; mt < 2; mt++) {
        int r0 = wm * 32 + mt * 16 + qr;
        int sA = tile + r0, sB = tile + r0 + 8;
#pragma unroll
        for (int nt = 0; nt < 8; nt++) {
            int col = wn * 64 + nt * 8 + qc * 2;
            if (sA < N) {
                float2* p = (float2*)(outp + (size_t)sA * BB + col);
                if (MODE == 2) {
                    float2 v = *p;
                    v.x += acc[mt][nt][0]; v.y += acc[mt][nt][1];
                    *p = v;
                } else {
                    *p = make_float2(acc[mt][nt][0], acc[mt][nt][1]);
                }
                if (MODE == 1)
                    *(uint32_t*)(g_mid16 + (size_t)sA * BB + col) =
                        cvt2(acc[mt][nt][0], acc[mt][nt][1]);
            }
            if (sB < N) {
                float2* p = (float2*)(outp + (size_t)sB * BB + col);
                if (MODE == 2) {
                    float2 v = *p;
                    v.x += acc[mt][nt][2]; v.y += acc[mt][nt][3];
                    *p = v;
                } else {
                    *p = make_float2(acc[mt][nt][2], acc[mt][nt][3]);
                }
                if (MODE == 1)
                    *(uint32_t*)(g_mid16 + (size_t)sB * BB + col) =
                        cvt2(acc[mt][nt][2], acc[mt][nt][3]);
            }
        }
    }
}

// ---------------------------------------------------------------------------
extern "C" void kernel_launch(void* const* d_in, const int* in_sizes, int n_in,
                              void* d_out, int out_size) {
    const float* feat   = (const float*)d_in[0];
    const float* gamma1 = (const float*)d_in[1];
    const float* beta1  = (const float*)d_in[2];
    const float* W1     = (const float*)d_in[3];
    const float* gamma2 = (const float*)d_in[4];
    const float* beta2  = (const float*)d_in[5];
    const float* W2     = (const float*)d_in[6];
    const float* Wnin   = (const float*)d_in[7];
    const int*   nbr    = (const int*)d_in[8];
    const void*  mask   = d_in[9];
    float*       out    = (float*)d_out;

    const int N = in_sizes[0] / AA;

    float *p_out1, *p_s1, *p_b1, *p_s2, *p_b2;
    unsigned short *p_f16, *p_m16;
    cudaGetSymbolAddress((void**)&p_out1, g_out1);
    cudaGetSymbolAddress((void**)&p_s1,   g_s1);
    cudaGetSymbolAddress((void**)&p_b1,   g_b1);
    cudaGetSymbolAddress((void**)&p_s2,   g_s2);
    cudaGetSymbolAddress((void**)&p_b2,   g_b2);
    cudaGetSymbolAddress((void**)&p_f16,  g_feat16);
    cudaGetSymbolAddress((void**)&p_m16,  g_mid16);

    const int gtiles = (N + 127) / 128;
    const int wtot   = KK * 2 * 128 * 16 + KK * 4 * 128 * 16 + 2 * 128 * 16;
    const int n4     = N * AA / 4;

    // mask dtype detect, gather-index precompute, feat fp16, weight pack
    k_detect<<<1, 256>>>((const unsigned char*)mask);
    k_gidx<<<(N + 255) / 256, 256>>>(nbr, mask, N);
    k_prep<<<(n4 + 255) / 256, 256>>>(feat, n4);
    k_wcvt<<<(wtot + 255) / 256, 256>>>(W1, W2, Wnin);

    // BN1 folded affine (stats on original fp32 feat)
    k_stats<AA, 4><<<PB, dim3(AA, 4)>>>(feat, N);
    k_fin<AA><<<1, dim3(AA, 8)>>>(gamma1, beta1, p_s1, p_b1, N);

    // conv1 -> g_out1 (fp32) + g_mid16 (fp16)
    k_conv<AA, 1><<<gtiles, 256>>>(p_f16, p_out1, N);

    // BN2 folded affine (stats on fp32 mid)
    k_stats<BB, 2><<<PB, dim3(BB, 2)>>>(p_out1, N);
    k_fin<BB><<<1, dim3(BB, 8)>>>(gamma2, beta2, p_s2, p_b2, N);

    // NiN shortcut (dense, initializes out), then conv2 RMW-adds
    k_conv<AA, 0><<<gtiles, 256>>>(p_f16, out, N);
    k_conv<BB, 2><<<gtiles, 256>>>(p_m16, out, N);
}